// round 11
// baseline (speedup 1.0000x reference)
#include <cuda_runtime.h>
#include <cuda_bf16.h>
#include <cuda_fp16.h>
#include <cstdint>

#define BNUM 2
#define SLEN 2048
#define DDIM 1024
#define HNUM 16
#define DKQ  64
#define WPD  36     // attn word pitch: 32 data words + 4 pad
#define PPD  20     // proj word pitch: 16 data words + 4 pad

// NOTE: k-dimension of all packed-fp16/bf16 operands is PERMUTED: within each
// 8-word (16-element) block, word w sits at position (w<4 ? 2w : 2(w-4)+1).
// Both operands of every dot product share the permutation -> results invariant.

// fp32 proj outputs [B,H,S,DK]
__device__ float    g_q[BNUM*HNUM*SLEN*DKQ];
__device__ float    g_k[BNUM*HNUM*SLEN*DKQ];
__device__ float    g_v[BNUM*HNUM*SLEN*DKQ];
__device__ uint32_t g_wt16[3][DDIM*DDIM/2];          // packed fp16 Wt[n][k], k-permuted
__device__ uint32_t g_af16[3][BNUM*SLEN*DDIM/2];     // packed fp16 inputs, k-permuted
__device__ uint32_t g_qhi[BNUM*HNUM*SLEN*DKQ/2];     // bf16x2 hi, Q*0.125, dk-permuted
__device__ uint32_t g_qlo[BNUM*HNUM*SLEN*DKQ/2];
__device__ uint32_t g_khi[BNUM*HNUM*SLEN*DKQ/2];
__device__ uint32_t g_klo[BNUM*HNUM*SLEN*DKQ/2];
__device__ uint32_t g_vt2[BNUM*HNUM*DKQ*SLEN/2];     // fp16x2 [bh][d][s_pair] (unpermuted)

// ---------------- helpers ----------------
__device__ __forceinline__ uint32_t smem_u32(const void* p) {
    uint32_t a;
    asm("{ .reg .u64 t; cvta.to.shared.u64 t, %1; cvt.u32.u64 %0, t; }"
        : "=r"(a) : "l"(p));
    return a;
}
__device__ __forceinline__ void cp16(uint32_t dst, const void* src) {
    asm volatile("cp.async.cg.shared.global [%0], [%1], 16;"
                 :: "r"(dst), "l"(src));
}
#define CP_COMMIT() asm volatile("cp.async.commit_group;" ::: "memory")
#define CP_WAIT1()  asm volatile("cp.async.wait_group 1;" ::: "memory")
#define CP_WAIT0()  asm volatile("cp.async.wait_group 0;" ::: "memory")

__device__ __forceinline__ void mma_bf16(
    float& d0, float& d1, float& d2, float& d3,
    uint32_t a0, uint32_t a1, uint32_t a2, uint32_t a3,
    uint32_t b0, uint32_t b1)
{
    asm volatile(
        "mma.sync.aligned.m16n8k16.row.col.f32.bf16.bf16.f32 "
        "{%0,%1,%2,%3}, {%4,%5,%6,%7}, {%8,%9}, {%0,%1,%2,%3};"
        : "+f"(d0), "+f"(d1), "+f"(d2), "+f"(d3)
        : "r"(a0), "r"(a1), "r"(a2), "r"(a3), "r"(b0), "r"(b1));
}
__device__ __forceinline__ void mma_fp16(
    float& d0, float& d1, float& d2, float& d3,
    uint32_t a0, uint32_t a1, uint32_t a2, uint32_t a3,
    uint32_t b0, uint32_t b1)
{
    asm volatile(
        "mma.sync.aligned.m16n8k16.row.col.f32.f16.f16.f32 "
        "{%0,%1,%2,%3}, {%4,%5,%6,%7}, {%8,%9}, {%0,%1,%2,%3};"
        : "+f"(d0), "+f"(d1), "+f"(d2), "+f"(d3)
        : "r"(a0), "r"(a1), "r"(a2), "r"(a3), "r"(b0), "r"(b1));
}
__device__ __forceinline__ void split_pack_bf16(
    float x0, float x1, uint32_t& whi, uint32_t& wlo)
{
    __nv_bfloat16 h0 = __float2bfloat16(x0);
    __nv_bfloat16 h1 = __float2bfloat16(x1);
    float r0 = x0 - __bfloat162float(h0);
    float r1 = x1 - __bfloat162float(h1);
    __nv_bfloat16 l0 = __float2bfloat16(r0);
    __nv_bfloat16 l1 = __float2bfloat16(r1);
    whi = (uint32_t)__bfloat16_as_ushort(h0) |
          ((uint32_t)__bfloat16_as_ushort(h1) << 16);
    wlo = (uint32_t)__bfloat16_as_ushort(l0) |
          ((uint32_t)__bfloat16_as_ushort(l1) << 16);
}
__device__ __forceinline__ uint32_t pack_h2(float a, float b) {
    __half2 h = __floats2half2_rn(a, b);
    return *(uint32_t*)&h;
}

// ---------------- pre-pass: inputs fp32 -> packed fp16, k-permuted ----------------
// Out word-pair i covers permuted positions (2i, 2i+1) of an 8-word block:
// sources = block floats [2j, 2j+1] and [2j+8, 2j+9], j = i & 3.
__global__ __launch_bounds__(256) void cvt_f16_kernel(
    const float2* __restrict__ q, const float2* __restrict__ k,
    const float2* __restrict__ v,
    uint2* __restrict__ oq, uint2* __restrict__ ok, uint2* __restrict__ ov, int n2)
{
    int i = blockIdx.x * blockDim.x + threadIdx.x;
    if (i >= n2) return;
    const float2* in = (blockIdx.y == 0) ? q : (blockIdx.y == 1) ? k : v;
    uint2* out       = (blockIdx.y == 0) ? oq : (blockIdx.y == 1) ? ok : ov;
    int blk = i >> 2, j = i & 3;
    float2 e = in[blk*8 + j];
    float2 o = in[blk*8 + j + 4];
    uint2 w = { pack_h2(e.x, e.y), pack_h2(o.x, o.y) };
    out[i] = w;
}

// ---------------- fused weight transpose + fp16 pack, k-permuted ----------------
__global__ __launch_bounds__(256) void transpose_pack_kernel(
    const float* __restrict__ in, uint32_t* __restrict__ out)
{
    __shared__ float t[32][33];
    const int tx = threadIdx.x, ty = threadIdx.y;
    int x = blockIdx.x*32 + tx;
    int y0 = blockIdx.y*32;
#pragma unroll
    for (int j = 0; j < 32; j += 8)
        t[ty + j][tx] = in[(size_t)(y0 + ty + j)*DDIM + x];
    __syncthreads();
    const int tid = ty * 32 + tx;
#pragma unroll
    for (int i = 0; i < 2; i++) {
        int idx = tid + i * 256;          // 0..511 = 32 rows x 16 out words
        int row = idx >> 4, wrd = idx & 15;
        int blk = wrd >> 3, wi = wrd & 7;
        int src0 = blk*16 + 2*(wi >> 1) + ((wi & 1) ? 8 : 0);
        uint32_t w = pack_h2(t[src0][row], t[src0 + 1][row]);
        out[(size_t)(blockIdx.x*32 + row)*(DDIM/2) + blockIdx.y*16 + wrd] = w;
    }
}

// ---------------- pre-pass: split Q/K into packed bf16 hi/lo, dk-permuted ----------------
__global__ __launch_bounds__(256) void split_qk_kernel(
    const float2* __restrict__ q_src, const float2* __restrict__ k_src,
    uint32_t* __restrict__ qhi, uint32_t* __restrict__ qlo,
    uint32_t* __restrict__ khi, uint32_t* __restrict__ klo, int nw)
{
    int i = blockIdx.x * blockDim.x + threadIdx.x;
    if (i >= nw) return;
    int blk = i >> 3, wi = i & 7;
    int src = blk*8 + (wi >> 1) + ((wi & 1) ? 4 : 0);
    if (blockIdx.y == 0) {
        float2 v = q_src[src];
        split_pack_bf16(v.x * 0.125f, v.y * 0.125f, qhi[i], qlo[i]);
    } else {
        float2 v = k_src[src];
        split_pack_bf16(v.x, v.y, khi[i], klo[i]);
    }
}

// ---------------- pre-pass: V -> packed fp16x2 transposed (unpermuted) ----------------
__global__ __launch_bounds__(128) void vt_kernel(
    const float* __restrict__ V, uint32_t* __restrict__ vt2)
{
    __shared__ float sm[64*68];
    const int tid = threadIdx.x;
    const int bh  = blockIdx.x;
    const int st  = blockIdx.y;
    const float* Vb = V + ((size_t)bh * SLEN + (size_t)st * 64) * DKQ;
#pragma unroll
    for (int it = 0; it < 8; it++) {
        int f = tid + it * 128;
        int rv = f & 63, cv = (f >> 6) << 2;
        float4 vv = *(const float4*)(Vb + rv * DKQ + cv);
        sm[(cv+0)*68 + rv] = vv.x;
        sm[(cv+1)*68 + rv] = vv.y;
        sm[(cv+2)*68 + rv] = vv.z;
        sm[(cv+3)*68 + rv] = vv.w;
    }
    __syncthreads();
#pragma unroll
    for (int it = 0; it < 16; it++) {
        int f = tid + it * 128;
        int d = f >> 5, sw = f & 31;
        uint32_t w = pack_h2(sm[d*68 + 2*sw], sm[d*68 + 2*sw + 1]);
        vt2[((size_t)bh * DKQ + d) * (SLEN/2) + st * 32 + sw] = w;
    }
}

// ---------------- fp16 HMMA projection, LDS.64 fragments ----------------
__global__ __launch_bounds__(256, 2) void proj_mma_kernel(
    const uint32_t* __restrict__ A0, const uint32_t* __restrict__ A1, const uint32_t* __restrict__ A2,
    const uint32_t* __restrict__ W0, const uint32_t* __restrict__ W1, const uint32_t* __restrict__ W2,
    const float* __restrict__ bias0, const float* __restrict__ bias1, const float* __restrict__ bias2,
    float* __restrict__ o0, float* __restrict__ o1, float* __restrict__ o2)
{
    extern __shared__ uint32_t psm[];        // As[2][128][PPD] | Bs[2][128][PPD]
    uint32_t* As = psm;
    uint32_t* Bs = psm + 2*128*PPD;
    const uint32_t as_u = smem_u32(As);
    const uint32_t bs_u = smem_u32(Bs);

    const int z = blockIdx.z;
    const uint32_t* A  = (z == 0) ? A0 : (z == 1) ? A1 : A2;
    const uint32_t* Wt = (z == 0) ? W0 : (z == 1) ? W1 : W2;
    const float* bias  = (z == 0) ? bias0 : (z == 1) ? bias1 : bias2;
    float*       out   = (z == 0) ? o0 : (z == 1) ? o1 : o2;

    const int tid  = threadIdx.x;
    const int wid  = tid >> 5;
    const int lane = tid & 31;
    const int lr   = lane >> 2;
    const int lc   = lane & 3;
    const int wm   = (wid >> 2) * 64;
    const int wn   = (wid & 3) * 32;
    const int col0 = blockIdx.x << 7;
    const int row0 = blockIdx.y << 7;

    const uint32_t* Abase = A  + (size_t)row0 * (DDIM/2);
    const uint32_t* Bbase = Wt + (size_t)col0 * (DDIM/2);

    auto issue = [&](int c, int s) {
#pragma unroll
        for (int it = 0; it < 2; it++) {
            int f = tid + it * 256;
            int r = f >> 2;
            int o = (f & 3) * 16;
            uint32_t d = (uint32_t)((s*128 + r) * (PPD*4)) + o;
            cp16(as_u + d, (const char*)(Abase + (size_t)r * (DDIM/2) + c*16) + o);
            cp16(bs_u + d, (const char*)(Bbase + (size_t)r * (DDIM/2) + c*16) + o);
        }
    };

    float acc[4][4][4];
#pragma unroll
    for (int mt = 0; mt < 4; mt++)
#pragma unroll
        for (int nt = 0; nt < 4; nt++)
#pragma unroll
            for (int i = 0; i < 4; i++) acc[mt][nt][i] = 0.f;

    issue(0, 0); CP_COMMIT();

    for (int c = 0; c < 32; c++) {
        const int s = c & 1;
        __syncthreads();
        if (c < 31) { issue(c + 1, s ^ 1); CP_COMMIT(); CP_WAIT1(); }
        else        { CP_WAIT0(); }
        __syncthreads();

        const uint32_t* Ast = As + s*128*PPD;
        const uint32_t* Bst = Bs + s*128*PPD;
#pragma unroll
        for (int ks = 0; ks < 2; ks++) {
            const int k8 = ks * 8 + 2*lc;     // permuted: (lc, lc+4) adjacent
            uint32_t a[4][4];
#pragma unroll
            for (int mt = 0; mt < 4; mt++) {
                int r = wm + mt * 16 + lr;
                uint2 u0 = *(const uint2*)&Ast[r*PPD + k8];
                uint2 u1 = *(const uint2*)&Ast[(r+8)*PPD + k8];
                a[mt][0] = u0.x; a[mt][2] = u0.y;
                a[mt][1] = u1.x; a[mt][3] = u1.y;
            }
#pragma unroll
            for (int nt = 0; nt < 4; nt++) {
                int n = wn + nt * 8 + lr;
                uint2 b = *(const uint2*)&Bst[n*PPD + k8];
#pragma unroll
                for (int mt = 0; mt < 4; mt++)
                    mma_fp16(acc[mt][nt][0], acc[mt][nt][1],
                             acc[mt][nt][2], acc[mt][nt][3],
                             a[mt][0], a[mt][1], a[mt][2], a[mt][3], b.x, b.y);
            }
        }
    }

#pragma unroll
    for (int mt = 0; mt < 4; mt++) {
#pragma unroll
        for (int nt = 0; nt < 4; nt++) {
            int col = col0 + wn + nt * 8 + 2 * lc;
            float2 bb = *(const float2*)(bias + col);
            int head = col >> 6;
            int dk   = col & 63;
#pragma unroll
            for (int h = 0; h < 2; h++) {
                int row = row0 + wm + mt * 16 + lr + h * 8;
                int bi  = row >> 11;
                int si  = row & (SLEN - 1);
                float2 v = { acc[mt][nt][2*h + 0] + bb.x,
                             acc[mt][nt][2*h + 1] + bb.y };
                *(float2*)(out + ((size_t)(bi * HNUM + head) * SLEN + si) * DKQ + dk) = v;
            }
        }
    }
}

// ---------------- cp.async flash attention, LDS.64 QK fragments ----------------
// Smem word offsets: Qh 0 | Ql 2304 | stage s: Kh 4608+6912s, Kl +2304, Vt +4608 | Ps 18432
__global__ __launch_bounds__(128) void attn_mma_kernel(
    const uint32_t* __restrict__ Qhi_g, const uint32_t* __restrict__ Qlo_g,
    const uint32_t* __restrict__ Khi_g, const uint32_t* __restrict__ Klo_g,
    const uint32_t* __restrict__ Vt_g,  float* __restrict__ out)
{
    extern __shared__ uint32_t sm[];
    uint32_t* Qh = sm;
    uint32_t* Ql = sm + 2304;
    uint32_t* Ps = sm + 18432;
    const uint32_t sm_u = smem_u32(sm);

    const int tid  = threadIdx.x;
    const int w    = tid >> 5;
    const int lane = tid & 31;
    const int lr   = lane >> 2;
    const int lc   = lane & 3;
    const int bh   = blockIdx.x;
    const int qt   = (gridDim.y - 1) - blockIdx.y;

    const uint32_t* Qh_src = Qhi_g + ((size_t)bh * SLEN + (size_t)qt * 64) * 32;
    const uint32_t* Ql_src = Qlo_g + ((size_t)bh * SLEN + (size_t)qt * 64) * 32;

    auto issue_kv = [&](int kt, int s) {
        const uint32_t* Kh_s = Khi_g + ((size_t)bh * SLEN + (size_t)kt * 64) * 32;
        const uint32_t* Kl_s = Klo_g + ((size_t)bh * SLEN + (size_t)kt * 64) * 32;
        const uint32_t* Vt_s = Vt_g  + (size_t)bh * DKQ * (SLEN/2) + (size_t)kt * 32;
        const uint32_t kb = sm_u + (uint32_t)(4608 + s*6912) * 4;
#pragma unroll
        for (int it = 0; it < 4; it++) {
            int f = tid + it * 128;
            int r = f >> 3;
            int o = (f & 7) * 16;
            uint32_t d = (uint32_t)(r * (WPD*4)) + o;
            cp16(kb + d,            (const char*)(Kh_s + (size_t)r * 32) + o);
            cp16(kb + 2304*4 + d,   (const char*)(Kl_s + (size_t)r * 32) + o);
            cp16(kb + 4608*4 + d,   (const char*)(Vt_s + (size_t)r * (SLEN/2)) + o);
        }
    };

#pragma unroll
    for (int it = 0; it < 4; it++) {
        int f = tid + it * 128;
        int r = f >> 3;
        int o = (f & 7) * 16;
        uint32_t d = (uint32_t)(r * (WPD*4)) + o;
        cp16(sm_u + d,          (const char*)(Qh_src + (size_t)r * 32) + o);
        cp16(sm_u + 2304*4 + d, (const char*)(Ql_src + (size_t)r * 32) + o);
    }
    issue_kv(0, 0);
    CP_COMMIT();

    float accO[8][4];
#pragma unroll
    for (int nf = 0; nf < 8; nf++)
#pragma unroll
        for (int i = 0; i < 4; i++) accO[nf][i] = 0.f;
    float mrow[2] = { -1e30f, -1e30f };
    float lrow[2] = { 0.f, 0.f };

    const int qrow0 = qt*64 + w*16 + lr;
    const int qbw   = (w*16 + lr) * WPD;

    for (int kt = 0; kt <= qt; kt++) {
        const int s = kt & 1;
        __syncthreads();
        if (kt < qt) { issue_kv(kt + 1, s ^ 1); CP_COMMIT(); CP_WAIT1(); }
        else         { CP_WAIT0(); }
        __syncthreads();

        const uint32_t* Khs = sm + 4608 + s*6912;
        const uint32_t* Kls = Khs + 2304;
        const uint32_t* Vts = Khs + 4608;

        // ---- scores: bf16x2 QK^T (permuted dk -> uint2 fragment loads) ----
        float accS[8][4];
#pragma unroll
        for (int nf = 0; nf < 8; nf++)
#pragma unroll
            for (int i = 0; i < 4; i++) accS[nf][i] = 0.f;

#pragma unroll
        for (int ks = 0; ks < 4; ks++) {
            const int k8 = ks * 8 + 2*lc;
            uint2 qh0 = *(const uint2*)&Qh[qbw + k8];           // (ah0, ah2)
            uint2 qh1 = *(const uint2*)&Qh[qbw + 8*WPD + k8];   // (ah1, ah3)
            uint2 ql0 = *(const uint2*)&Ql[qbw + k8];
            uint2 ql1 = *(const uint2*)&Ql[qbw + 8*WPD + k8];
#pragma unroll
            for (int nf = 0; nf < 8; nf++) {
                int nb = (nf*8 + lr) * WPD + k8;
                uint2 kh = *(const uint2*)&Khs[nb];
                uint2 kl = *(const uint2*)&Kls[nb];
                mma_bf16(accS[nf][0], accS[nf][1], accS[nf][2], accS[nf][3],
                         qh0.x, qh1.x, qh0.y, qh1.y, kh.x, kh.y);
                mma_bf16(accS[nf][0], accS[nf][1], accS[nf][2], accS[nf][3],
                         qh0.x, qh1.x, qh0.y, qh1.y, kl.x, kl.y);
                mma_bf16(accS[nf][0], accS[nf][1], accS[nf][2], accS[nf][3],
                         ql0.x, ql1.x, ql0.y, ql1.y, kh.x, kh.y);
            }
        }

        if (kt == qt) {
#pragma unroll
            for (int nf = 0; nf < 8; nf++) {
                int gc = kt*64 + nf*8 + 2*lc;
                if (gc     > qrow0)     accS[nf][0] = -1e30f;
                if (gc + 1 > qrow0)     accS[nf][1] = -1e30f;
                if (gc     > qrow0 + 8) accS[nf][2] = -1e30f;
                if (gc + 1 > qrow0 + 8) accS[nf][3] = -1e30f;
            }
        }

        // ---- online softmax; P packed fp16x2 (unpermuted keys) ----
#pragma unroll
        for (int h = 0; h < 2; h++) {
            const int i0 = 2*h, i1 = 2*h + 1;
            float rmax = accS[0][i0];
#pragma unroll
            for (int nf = 0; nf < 8; nf++) {
                rmax = fmaxf(rmax, accS[nf][i0]);
                rmax = fmaxf(rmax, accS[nf][i1]);
            }
            rmax = fmaxf(rmax, __shfl_xor_sync(0xffffffffu, rmax, 1));
            rmax = fmaxf(rmax, __shfl_xor_sync(0xffffffffu, rmax, 2));
            float mn   = fmaxf(mrow[h], rmax);
            float corr = __expf(mrow[h] - mn);
            mrow[h] = mn;
            float rsum = 0.f;
            const int pb = qbw + h*8*WPD;
#pragma unroll
            for (int nf = 0; nf < 8; nf++) {
                float e0 = __expf(accS[nf][i0] - mn);
                float e1 = __expf(accS[nf][i1] - mn);
                __half2 hp = __floats2half2_rn(e0, e1);
                Ps[pb + nf*4 + lc] = *(uint32_t*)&hp;
                rsum += __low2float(hp) + __high2float(hp);
                accO[nf][i0] *= corr;
                accO[nf][i1] *= corr;
            }
            rsum += __shfl_xor_sync(0xffffffffu, rsum, 1);
            rsum += __shfl_xor_sync(0xffffffffu, rsum, 2);
            lrow[h] = lrow[h] * corr + rsum;
        }
        __syncwarp();

        // ---- accO += P @ V (fp16, unpermuted) ----
#pragma unroll
        for (int ks = 0; ks < 4; ks++) {
            const int k8 = ks * 8;
            uint32_t a0 = Ps[qbw + k8 + lc];
            uint32_t a1 = Ps[qbw + 8*WPD + k8 + lc];
            uint32_t a2 = Ps[qbw + k8 + lc + 4];
            uint32_t a3 = Ps[qbw + 8*WPD + k8 + lc + 4];
#pragma unroll
            for (int nf = 0; nf < 8; nf++) {
                int nb = (nf*8 + lr) * WPD + k8 + lc;
                uint32_t b0 = Vts[nb], b1 = Vts[nb + 4];
                mma_fp16(accO[nf][0], accO[nf][1], accO[nf][2], accO[nf][3],
                         a0, a1, a2, a3, b0, b1);
            }
        }
    }

    // ---- epilogue: out[B,S,D] ----
    const int b = bh >> 4, h = bh & 15;
    const float inv0 = 1.f / lrow[0];
    const float inv1 = 1.f / lrow[1];
    const int s0 = qt*64 + w*16 + lr;
    const int s1 = s0 + 8;
#pragma unroll
    for (int nf = 0; nf < 8; nf++) {
        int col = h*DKQ + nf*8 + 2*lc;
        float2 v0 = { accO[nf][0] * inv0, accO[nf][1] * inv0 };
        float2 v1 = { accO[nf][2] * inv1, accO[nf][3] * inv1 };
        *(float2*)(out + ((size_t)b * SLEN + s0) * DDIM + col) = v0;
        *(float2*)(out + ((size_t)b * SLEN + s1) * DDIM + col) = v1;
    }
}

extern "C" void kernel_launch(void* const* d_in, const int* in_sizes, int n_in,
                              void* d_out, int out_size) {
    const float* q  = (const float*)d_in[0];
    const float* k  = (const float*)d_in[1];
    const float* v  = (const float*)d_in[2];
    const float* Wq = (const float*)d_in[3];
    const float* bq = (const float*)d_in[4];
    const float* Wk = (const float*)d_in[5];
    const float* bk = (const float*)d_in[6];
    const float* Wv = (const float*)d_in[7];
    const float* bv = (const float*)d_in[8];
    float* out = (float*)d_out;

    float *gq, *gk, *gv;
    uint32_t *gwt16, *gaf16, *gqh, *gql, *gkh, *gkl, *gvt;
    cudaGetSymbolAddress((void**)&gq,    g_q);
    cudaGetSymbolAddress((void**)&gk,    g_k);
    cudaGetSymbolAddress((void**)&gv,    g_v);
    cudaGetSymbolAddress((void**)&gwt16, g_wt16);
    cudaGetSymbolAddress((void**)&gaf16, g_af16);
    cudaGetSymbolAddress((void**)&gqh,   g_qhi);
    cudaGetSymbolAddress((void**)&gql,   g_qlo);
    cudaGetSymbolAddress((void**)&gkh,   g_khi);
    cudaGetSymbolAddress((void**)&gkl,   g_klo);
    cudaGetSymbolAddress((void**)&gvt,   g_vt2);

    // Fused weight transpose + fp16 pack (k-permuted).
    dim3 tgrid(DDIM/32, DDIM/32), tblk(32, 8);
    transpose_pack_kernel<<<tgrid, tblk>>>(Wq, gwt16 + 0*DDIM*DDIM/2);
    transpose_pack_kernel<<<tgrid, tblk>>>(Wk, gwt16 + 1*DDIM*DDIM/2);
    transpose_pack_kernel<<<tgrid, tblk>>>(Wv, gwt16 + 2*DDIM*DDIM/2);

    // Inputs -> packed fp16 (k-permuted), single launch.
    const size_t NA = (size_t)BNUM*SLEN*DDIM;
    const int n2 = (int)(NA/4);   // uint2 outputs
    cvt_f16_kernel<<<dim3((n2+255)/256, 3), 256>>>(
        (const float2*)q, (const float2*)k, (const float2*)v,
        (uint2*)(gaf16 + 0*NA/2), (uint2*)(gaf16 + 1*NA/2), (uint2*)(gaf16 + 2*NA/2), n2);

    // Projections.
    const int proj_smem = 2 * 2 * 128 * PPD * 4;  // 40960
    cudaFuncSetAttribute(proj_mma_kernel,
        cudaFuncAttributeMaxDynamicSharedMemorySize, proj_smem);
    dim3 pgrid(DDIM/128, (BNUM*SLEN)/128, 3);
    proj_mma_kernel<<<pgrid, 256, proj_smem>>>(
        gaf16 + 0*NA/2, gaf16 + 1*NA/2, gaf16 + 2*NA/2,
        gwt16 + 0*DDIM*DDIM/2, gwt16 + 1*DDIM*DDIM/2, gwt16 + 2*DDIM*DDIM/2,
        bq, bk, bv,
        gq, gk, gv);

    // Attention pre-passes: Q/K split (dk-permuted), V pack-transpose.
    const int nw = BNUM*HNUM*SLEN*DKQ/2;
    split_qk_kernel<<<dim3((nw+255)/256, 2), 256>>>(
        (const float2*)gq, (const float2*)gk, gqh, gql, gkh, gkl, nw);
    vt_kernel<<<dim3(BNUM*HNUM, SLEN/64), 128>>>(gv, gvt);

    // Attention.
    const int attn_smem = (18432 + 2304) * 4;     // 82944
    cudaFuncSetAttribute(attn_mma_kernel,
        cudaFuncAttributeMaxDynamicSharedMemorySize, attn_smem);
    attn_mma_kernel<<<dim3(BNUM*HNUM, SLEN/64), 128, attn_smem>>>(
        gqh, gql, gkh, gkl, gvt, out);
}

// round 12
// speedup vs baseline: 1.2292x; 1.2292x over previous
#include <cuda_runtime.h>
#include <cuda_bf16.h>
#include <cuda_fp16.h>
#include <cstdint>

#define BNUM 2
#define SLEN 2048
#define DDIM 1024
#define HNUM 16
#define DKQ  64
#define WPD  36     // attn word pitch: 32 data words + 4 pad (banks 4*lr+lc)
#define PPD  20     // proj word pitch: 16 data words + 4 pad

// fp32 proj outputs [B,H,S,DK]
__device__ float    g_q[BNUM*HNUM*SLEN*DKQ];
__device__ float    g_k[BNUM*HNUM*SLEN*DKQ];
__device__ float    g_v[BNUM*HNUM*SLEN*DKQ];
__device__ uint32_t g_wt16[3][DDIM*DDIM/2];          // packed fp16 Wt[n][k]
__device__ uint32_t g_af16[3][BNUM*SLEN*DDIM/2];     // packed fp16 inputs
// attention-ready tiles
__device__ uint32_t g_qhi[BNUM*HNUM*SLEN*DKQ/2];     // bf16x2 hi, Q*0.125
__device__ uint32_t g_qlo[BNUM*HNUM*SLEN*DKQ/2];
__device__ uint32_t g_khi[BNUM*HNUM*SLEN*DKQ/2];
__device__ uint32_t g_klo[BNUM*HNUM*SLEN*DKQ/2];
__device__ uint32_t g_vt2[BNUM*HNUM*DKQ*SLEN/2];     // fp16x2 [bh][d][s_pair]

// ---------------- helpers ----------------
__device__ __forceinline__ uint32_t smem_u32(const void* p) {
    uint32_t a;
    asm("{ .reg .u64 t; cvta.to.shared.u64 t, %1; cvt.u32.u64 %0, t; }"
        : "=r"(a) : "l"(p));
    return a;
}
__device__ __forceinline__ void cp16(uint32_t dst, const void* src) {
    asm volatile("cp.async.cg.shared.global [%0], [%1], 16;"
                 :: "r"(dst), "l"(src));
}
#define CP_COMMIT() asm volatile("cp.async.commit_group;" ::: "memory")
#define CP_WAIT1()  asm volatile("cp.async.wait_group 1;" ::: "memory")
#define CP_WAIT0()  asm volatile("cp.async.wait_group 0;" ::: "memory")

__device__ __forceinline__ void mma_bf16(
    float& d0, float& d1, float& d2, float& d3,
    uint32_t a0, uint32_t a1, uint32_t a2, uint32_t a3,
    uint32_t b0, uint32_t b1)
{
    asm volatile(
        "mma.sync.aligned.m16n8k16.row.col.f32.bf16.bf16.f32 "
        "{%0,%1,%2,%3}, {%4,%5,%6,%7}, {%8,%9}, {%0,%1,%2,%3};"
        : "+f"(d0), "+f"(d1), "+f"(d2), "+f"(d3)
        : "r"(a0), "r"(a1), "r"(a2), "r"(a3), "r"(b0), "r"(b1));
}
__device__ __forceinline__ void mma_fp16(
    float& d0, float& d1, float& d2, float& d3,
    uint32_t a0, uint32_t a1, uint32_t a2, uint32_t a3,
    uint32_t b0, uint32_t b1)
{
    asm volatile(
        "mma.sync.aligned.m16n8k16.row.col.f32.f16.f16.f32 "
        "{%0,%1,%2,%3}, {%4,%5,%6,%7}, {%8,%9}, {%0,%1,%2,%3};"
        : "+f"(d0), "+f"(d1), "+f"(d2), "+f"(d3)
        : "r"(a0), "r"(a1), "r"(a2), "r"(a3), "r"(b0), "r"(b1));
}
__device__ __forceinline__ void split_pack_bf16(
    float x0, float x1, uint32_t& whi, uint32_t& wlo)
{
    __nv_bfloat16 h0 = __float2bfloat16(x0);
    __nv_bfloat16 h1 = __float2bfloat16(x1);
    float r0 = x0 - __bfloat162float(h0);
    float r1 = x1 - __bfloat162float(h1);
    __nv_bfloat16 l0 = __float2bfloat16(r0);
    __nv_bfloat16 l1 = __float2bfloat16(r1);
    whi = (uint32_t)__bfloat16_as_ushort(h0) |
          ((uint32_t)__bfloat16_as_ushort(h1) << 16);
    wlo = (uint32_t)__bfloat16_as_ushort(l0) |
          ((uint32_t)__bfloat16_as_ushort(l1) << 16);
}
__device__ __forceinline__ uint32_t pack_h2(float a, float b) {
    __half2 h = __floats2half2_rn(a, b);
    return *(uint32_t*)&h;
}

// ---------------- pre-pass: inputs fp32 -> packed fp16 (3 arrays via y) ----------------
__global__ __launch_bounds__(256) void cvt_f16_kernel(
    const float4* __restrict__ q, const float4* __restrict__ k,
    const float4* __restrict__ v,
    uint2* __restrict__ oq, uint2* __restrict__ ok, uint2* __restrict__ ov, int n4)
{
    int i = blockIdx.x * blockDim.x + threadIdx.x;
    if (i >= n4) return;
    const float4* in = (blockIdx.y == 0) ? q : (blockIdx.y == 1) ? k : v;
    uint2* out       = (blockIdx.y == 0) ? oq : (blockIdx.y == 1) ? ok : ov;
    float4 x = in[i];
    uint2 o = { pack_h2(x.x, x.y), pack_h2(x.z, x.w) };
    out[i] = o;
}

// ---------------- fused weight transpose + fp16 pack, 3 weights via z ----------------
__global__ __launch_bounds__(256) void transpose_pack_kernel(
    const float* __restrict__ w0, const float* __restrict__ w1, const float* __restrict__ w2,
    uint32_t* __restrict__ o0, uint32_t* __restrict__ o1, uint32_t* __restrict__ o2)
{
    __shared__ float t[32][33];
    const float* in = (blockIdx.z == 0) ? w0 : (blockIdx.z == 1) ? w1 : w2;
    uint32_t* out   = (blockIdx.z == 0) ? o0 : (blockIdx.z == 1) ? o1 : o2;
    const int tx = threadIdx.x, ty = threadIdx.y;
    int x = blockIdx.x*32 + tx;
    int y0 = blockIdx.y*32;
#pragma unroll
    for (int j = 0; j < 32; j += 8)
        t[ty + j][tx] = in[(size_t)(y0 + ty + j)*DDIM + x];
    __syncthreads();
    const int tid = ty * 32 + tx;
#pragma unroll
    for (int i = 0; i < 2; i++) {
        int idx = tid + i * 256;          // 0..511 = 32 rows x 16 words
        int row = idx >> 4, wrd = idx & 15;
        uint32_t w = pack_h2(t[2*wrd][row], t[2*wrd + 1][row]);
        out[(size_t)(blockIdx.x*32 + row)*(DDIM/2) + blockIdx.y*16 + wrd] = w;
    }
}

// ---------------- pre-pass: split Q/K into packed bf16 hi/lo ----------------
__global__ __launch_bounds__(256) void split_qk_kernel(
    const float2* __restrict__ q_src, const float2* __restrict__ k_src,
    uint32_t* __restrict__ qhi, uint32_t* __restrict__ qlo,
    uint32_t* __restrict__ khi, uint32_t* __restrict__ klo, int nw)
{
    int i = blockIdx.x * blockDim.x + threadIdx.x;
    if (i >= nw) return;
    if (blockIdx.y == 0) {
        float2 v = q_src[i];
        split_pack_bf16(v.x * 0.125f, v.y * 0.125f, qhi[i], qlo[i]);
    } else {
        float2 v = k_src[i];
        split_pack_bf16(v.x, v.y, khi[i], klo[i]);
    }
}

// ---------------- pre-pass: V -> packed fp16x2 transposed [bh][d][s_pair] ----------------
__global__ __launch_bounds__(128) void vt_kernel(
    const float* __restrict__ V, uint32_t* __restrict__ vt2)
{
    __shared__ float sm[64*68];
    const int tid = threadIdx.x;
    const int bh  = blockIdx.x;
    const int st  = blockIdx.y;          // 64-key tile
    const float* Vb = V + ((size_t)bh * SLEN + (size_t)st * 64) * DKQ;
#pragma unroll
    for (int it = 0; it < 8; it++) {
        int f = tid + it * 128;
        int rv = f & 63, cv = (f >> 6) << 2;
        float4 vv = *(const float4*)(Vb + rv * DKQ + cv);
        sm[(cv+0)*68 + rv] = vv.x;
        sm[(cv+1)*68 + rv] = vv.y;
        sm[(cv+2)*68 + rv] = vv.z;
        sm[(cv+3)*68 + rv] = vv.w;
    }
    __syncthreads();
#pragma unroll
    for (int it = 0; it < 16; it++) {
        int f = tid + it * 128;          // 0..2047 = 64 d x 32 words
        int d = f >> 5, sw = f & 31;
        uint32_t w = pack_h2(sm[d*68 + 2*sw], sm[d*68 + 2*sw + 1]);
        vt2[((size_t)bh * DKQ + d) * (SLEN/2) + st * 32 + sw] = w;
    }
}

// ---------------- fp16 HMMA projection, 3 GEMMs merged on z (R8/R10) ----------------
__global__ __launch_bounds__(256, 2) void proj_mma_kernel(
    const uint32_t* __restrict__ A0, const uint32_t* __restrict__ A1, const uint32_t* __restrict__ A2,
    const uint32_t* __restrict__ W0, const uint32_t* __restrict__ W1, const uint32_t* __restrict__ W2,
    const float* __restrict__ bias0, const float* __restrict__ bias1, const float* __restrict__ bias2,
    float* __restrict__ o0, float* __restrict__ o1, float* __restrict__ o2)
{
    extern __shared__ uint32_t psm[];        // As[2][128][PPD] | Bs[2][128][PPD]
    uint32_t* As = psm;
    uint32_t* Bs = psm + 2*128*PPD;
    const uint32_t as_u = smem_u32(As);
    const uint32_t bs_u = smem_u32(Bs);

    const int z = blockIdx.z;
    const uint32_t* A  = (z == 0) ? A0 : (z == 1) ? A1 : A2;
    const uint32_t* Wt = (z == 0) ? W0 : (z == 1) ? W1 : W2;
    const float* bias  = (z == 0) ? bias0 : (z == 1) ? bias1 : bias2;
    float*       out   = (z == 0) ? o0 : (z == 1) ? o1 : o2;

    const int tid  = threadIdx.x;
    const int wid  = tid >> 5;
    const int lane = tid & 31;
    const int lr   = lane >> 2;
    const int lc   = lane & 3;
    const int wm   = (wid >> 2) * 64;
    const int wn   = (wid & 3) * 32;
    const int col0 = blockIdx.x << 7;
    const int row0 = blockIdx.y << 7;

    const uint32_t* Abase = A  + (size_t)row0 * (DDIM/2);
    const uint32_t* Bbase = Wt + (size_t)col0 * (DDIM/2);

    auto issue = [&](int c, int s) {
#pragma unroll
        for (int it = 0; it < 2; it++) {
            int f = tid + it * 256;          // 0..511 : 128 rows x 4 cp16
            int r = f >> 2;
            int o = (f & 3) * 16;
            uint32_t d = (uint32_t)((s*128 + r) * (PPD*4)) + o;
            cp16(as_u + d, (const char*)(Abase + (size_t)r * (DDIM/2) + c*16) + o);
            cp16(bs_u + d, (const char*)(Bbase + (size_t)r * (DDIM/2) + c*16) + o);
        }
    };

    float acc[4][4][4];
#pragma unroll
    for (int mt = 0; mt < 4; mt++)
#pragma unroll
        for (int nt = 0; nt < 4; nt++)
#pragma unroll
            for (int i = 0; i < 4; i++) acc[mt][nt][i] = 0.f;

    issue(0, 0); CP_COMMIT();

    for (int c = 0; c < 32; c++) {
        const int s = c & 1;
        __syncthreads();
        if (c < 31) { issue(c + 1, s ^ 1); CP_COMMIT(); CP_WAIT1(); }
        else        { CP_WAIT0(); }
        __syncthreads();

        const uint32_t* Ast = As + s*128*PPD;
        const uint32_t* Bst = Bs + s*128*PPD;
#pragma unroll
        for (int ks = 0; ks < 2; ks++) {
            const int k8 = ks * 8;
            uint32_t a[4][4];
#pragma unroll
            for (int mt = 0; mt < 4; mt++) {
                int r = wm + mt * 16 + lr;
                a[mt][0] = Ast[r*PPD + k8 + lc];
                a[mt][1] = Ast[(r+8)*PPD + k8 + lc];
                a[mt][2] = Ast[r*PPD + k8 + lc + 4];
                a[mt][3] = Ast[(r+8)*PPD + k8 + lc + 4];
            }
#pragma unroll
            for (int nt = 0; nt < 4; nt++) {
                int n = wn + nt * 8 + lr;
                uint32_t b0 = Bst[n*PPD + k8 + lc];
                uint32_t b1 = Bst[n*PPD + k8 + lc + 4];
#pragma unroll
                for (int mt = 0; mt < 4; mt++)
                    mma_fp16(acc[mt][nt][0], acc[mt][nt][1],
                             acc[mt][nt][2], acc[mt][nt][3],
                             a[mt][0], a[mt][1], a[mt][2], a[mt][3], b0, b1);
            }
        }
    }

#pragma unroll
    for (int mt = 0; mt < 4; mt++) {
#pragma unroll
        for (int nt = 0; nt < 4; nt++) {
            int col = col0 + wn + nt * 8 + 2 * lc;
            float2 bb = *(const float2*)(bias + col);
            int head = col >> 6;
            int dk   = col & 63;
#pragma unroll
            for (int h = 0; h < 2; h++) {
                int row = row0 + wm + mt * 16 + lr + h * 8;
                int bi  = row >> 11;
                int si  = row & (SLEN - 1);
                float2 v = { acc[mt][nt][2*h + 0] + bb.x,
                             acc[mt][nt][2*h + 1] + bb.y };
                *(float2*)(out + ((size_t)(bi * HNUM + head) * SLEN + si) * DKQ + dk) = v;
            }
        }
    }
}

// ---------------- cp.async flash attention: P in registers, Q hoisted ----------------
// Smem word offsets: Qh 0 | Ql 2304 | stage s: Kh 4608+6912s, Kl +2304, Vt +4608
// P never touches smem: thread (lr,lc)'s softmax outputs ARE its PV A-fragments.
__global__ __launch_bounds__(128) void attn_mma_kernel(
    const uint32_t* __restrict__ Qhi_g, const uint32_t* __restrict__ Qlo_g,
    const uint32_t* __restrict__ Khi_g, const uint32_t* __restrict__ Klo_g,
    const uint32_t* __restrict__ Vt_g,  float* __restrict__ out)
{
    extern __shared__ uint32_t sm[];
    uint32_t* Qh = sm;
    uint32_t* Ql = sm + 2304;
    const uint32_t sm_u = smem_u32(sm);

    const int tid  = threadIdx.x;
    const int w    = tid >> 5;
    const int lane = tid & 31;
    const int lr   = lane >> 2;
    const int lc   = lane & 3;
    const int bh   = blockIdx.x;
    const int qt   = (gridDim.y - 1) - blockIdx.y;

    const uint32_t* Qh_src = Qhi_g + ((size_t)bh * SLEN + (size_t)qt * 64) * 32;
    const uint32_t* Ql_src = Qlo_g + ((size_t)bh * SLEN + (size_t)qt * 64) * 32;

    auto issue_kv = [&](int kt, int s) {
        const uint32_t* Kh_s = Khi_g + ((size_t)bh * SLEN + (size_t)kt * 64) * 32;
        const uint32_t* Kl_s = Klo_g + ((size_t)bh * SLEN + (size_t)kt * 64) * 32;
        const uint32_t* Vt_s = Vt_g  + (size_t)bh * DKQ * (SLEN/2) + (size_t)kt * 32;
        const uint32_t kb = sm_u + (uint32_t)(4608 + s*6912) * 4;
#pragma unroll
        for (int it = 0; it < 4; it++) {
            int f = tid + it * 128;          // 0..511 : 64 rows x 8 cp16
            int r = f >> 3;
            int o = (f & 7) * 16;
            uint32_t d = (uint32_t)(r * (WPD*4)) + o;
            cp16(kb + d,            (const char*)(Kh_s + (size_t)r * 32) + o);
            cp16(kb + 2304*4 + d,   (const char*)(Kl_s + (size_t)r * 32) + o);
            cp16(kb + 4608*4 + d,   (const char*)(Vt_s + (size_t)r * (SLEN/2)) + o);
        }
    };

#pragma unroll
    for (int it = 0; it < 4; it++) {
        int f = tid + it * 128;
        int r = f >> 3;
        int o = (f & 7) * 16;
        uint32_t d = (uint32_t)(r * (WPD*4)) + o;
        cp16(sm_u + d,          (const char*)(Qh_src + (size_t)r * 32) + o);
        cp16(sm_u + 2304*4 + d, (const char*)(Ql_src + (size_t)r * 32) + o);
    }
    issue_kv(0, 0);
    CP_COMMIT();

    float accO[8][4];
#pragma unroll
    for (int nf = 0; nf < 8; nf++)
#pragma unroll
        for (int i = 0; i < 4; i++) accO[nf][i] = 0.f;
    float mrow[2] = { -1e30f, -1e30f };
    float lrow[2] = { 0.f, 0.f };

    uint32_t qh_r[4][4], ql_r[4][4];   // Q fragments, kt-invariant
    uint32_t pw[2][8];                 // packed P words (h, nf) = PV A-fragments

    const int qrow0 = qt*64 + w*16 + lr;
    const int qbw   = (w*16 + lr) * WPD;

    for (int kt = 0; kt <= qt; kt++) {
        const int s = kt & 1;
        __syncthreads();                     // stage-s^1 readers (kt-1) done
        if (kt < qt) { issue_kv(kt + 1, s ^ 1); CP_COMMIT(); CP_WAIT1(); }
        else         { CP_WAIT0(); }
        __syncthreads();                     // stage s (and Q at kt=0) visible

        if (kt == 0) {
#pragma unroll
            for (int ks = 0; ks < 4; ks++) {
                const int k8 = ks * 8;
                qh_r[ks][0] = Qh[qbw + k8 + lc];
                qh_r[ks][1] = Qh[qbw + 8*WPD + k8 + lc];
                qh_r[ks][2] = Qh[qbw + k8 + lc + 4];
                qh_r[ks][3] = Qh[qbw + 8*WPD + k8 + lc + 4];
                ql_r[ks][0] = Ql[qbw + k8 + lc];
                ql_r[ks][1] = Ql[qbw + 8*WPD + k8 + lc];
                ql_r[ks][2] = Ql[qbw + k8 + lc + 4];
                ql_r[ks][3] = Ql[qbw + 8*WPD + k8 + lc + 4];
            }
        }

        const uint32_t* Khs = sm + 4608 + s*6912;
        const uint32_t* Kls = Khs + 2304;
        const uint32_t* Vts = Khs + 4608;

        // ---- scores: bf16x2 QK^T ----
        float accS[8][4];
#pragma unroll
        for (int nf = 0; nf < 8; nf++)
#pragma unroll
            for (int i = 0; i < 4; i++) accS[nf][i] = 0.f;

#pragma unroll
        for (int ks = 0; ks < 4; ks++) {
            const int k8 = ks * 8;
#pragma unroll
            for (int nf = 0; nf < 8; nf++) {
                int nb = (nf*8 + lr) * WPD + k8 + lc;
                uint32_t bh0 = Khs[nb], bh1 = Khs[nb + 4];
                uint32_t bl0 = Kls[nb], bl1 = Kls[nb + 4];
                mma_bf16(accS[nf][0], accS[nf][1], accS[nf][2], accS[nf][3],
                         qh_r[ks][0], qh_r[ks][1], qh_r[ks][2], qh_r[ks][3], bh0, bh1);
                mma_bf16(accS[nf][0], accS[nf][1], accS[nf][2], accS[nf][3],
                         qh_r[ks][0], qh_r[ks][1], qh_r[ks][2], qh_r[ks][3], bl0, bl1);
                mma_bf16(accS[nf][0], accS[nf][1], accS[nf][2], accS[nf][3],
                         ql_r[ks][0], ql_r[ks][1], ql_r[ks][2], ql_r[ks][3], bh0, bh1);
            }
        }

        if (kt == qt) {
#pragma unroll
            for (int nf = 0; nf < 8; nf++) {
                int gc = kt*64 + nf*8 + 2*lc;
                if (gc     > qrow0)     accS[nf][0] = -1e30f;
                if (gc + 1 > qrow0)     accS[nf][1] = -1e30f;
                if (gc     > qrow0 + 8) accS[nf][2] = -1e30f;
                if (gc + 1 > qrow0 + 8) accS[nf][3] = -1e30f;
            }
        }

        // ---- online softmax; P kept in registers ----
#pragma unroll
        for (int h = 0; h < 2; h++) {
            const int i0 = 2*h, i1 = 2*h + 1;
            float rmax = accS[0][i0];
#pragma unroll
            for (int nf = 0; nf < 8; nf++) {
                rmax = fmaxf(rmax, accS[nf][i0]);
                rmax = fmaxf(rmax, accS[nf][i1]);
            }
            rmax = fmaxf(rmax, __shfl_xor_sync(0xffffffffu, rmax, 1));
            rmax = fmaxf(rmax, __shfl_xor_sync(0xffffffffu, rmax, 2));
            float mn   = fmaxf(mrow[h], rmax);
            float corr = __expf(mrow[h] - mn);
            mrow[h] = mn;
            float rsum = 0.f;
#pragma unroll
            for (int nf = 0; nf < 8; nf++) {
                float e0 = __expf(accS[nf][i0] - mn);
                float e1 = __expf(accS[nf][i1] - mn);
                __half2 hp = __floats2half2_rn(e0, e1);
                pw[h][nf] = *(uint32_t*)&hp;
                rsum += __low2float(hp) + __high2float(hp);
                accO[nf][i0] *= corr;
                accO[nf][i1] *= corr;
            }
            rsum += __shfl_xor_sync(0xffffffffu, rsum, 1);
            rsum += __shfl_xor_sync(0xffffffffu, rsum, 2);
            lrow[h] = lrow[h] * corr + rsum;
        }

        // ---- accO += P @ V (fp16); A-fragments ARE the pw registers ----
#pragma unroll
        for (int ks = 0; ks < 4; ks++) {
            const int k8 = ks * 8;
            uint32_t a0 = pw[0][2*ks];
            uint32_t a1 = pw[1][2*ks];
            uint32_t a2 = pw[0][2*ks + 1];
            uint32_t a3 = pw[1][2*ks + 1];
#pragma unroll
            for (int nf = 0; nf < 8; nf++) {
                int nb = (nf*8 + lr) * WPD + k8 + lc;
                uint32_t b0 = Vts[nb], b1 = Vts[nb + 4];
                mma_fp16(accO[nf][0], accO[nf][1], accO[nf][2], accO[nf][3],
                         a0, a1, a2, a3, b0, b1);
            }
        }
    }

    // ---- epilogue: out[B,S,D] ----
    const int b = bh >> 4, h = bh & 15;
    const float inv0 = 1.f / lrow[0];
    const float inv1 = 1.f / lrow[1];
    const int s0 = qt*64 + w*16 + lr;
    const int s1 = s0 + 8;
#pragma unroll
    for (int nf = 0; nf < 8; nf++) {
        int col = h*DKQ + nf*8 + 2*lc;
        float2 v0 = { accO[nf][0] * inv0, accO[nf][1] * inv0 };
        float2 v1 = { accO[nf][2] * inv1, accO[nf][3] * inv1 };
        *(float2*)(out + ((size_t)b * SLEN + s0) * DDIM + col) = v0;
        *(float2*)(out + ((size_t)b * SLEN + s1) * DDIM + col) = v1;
    }
}

extern "C" void kernel_launch(void* const* d_in, const int* in_sizes, int n_in,
                              void* d_out, int out_size) {
    const float* q  = (const float*)d_in[0];
    const float* k  = (const float*)d_in[1];
    const float* v  = (const float*)d_in[2];
    const float* Wq = (const float*)d_in[3];
    const float* bq = (const float*)d_in[4];
    const float* Wk = (const float*)d_in[5];
    const float* bk = (const float*)d_in[6];
    const float* Wv = (const float*)d_in[7];
    const float* bv = (const float*)d_in[8];
    float* out = (float*)d_out;

    float *gq, *gk, *gv;
    uint32_t *gwt16, *gaf16, *gqh, *gql, *gkh, *gkl, *gvt;
    cudaGetSymbolAddress((void**)&gq,    g_q);
    cudaGetSymbolAddress((void**)&gk,    g_k);
    cudaGetSymbolAddress((void**)&gv,    g_v);
    cudaGetSymbolAddress((void**)&gwt16, g_wt16);
    cudaGetSymbolAddress((void**)&gaf16, g_af16);
    cudaGetSymbolAddress((void**)&gqh,   g_qhi);
    cudaGetSymbolAddress((void**)&gql,   g_qlo);
    cudaGetSymbolAddress((void**)&gkh,   g_khi);
    cudaGetSymbolAddress((void**)&gkl,   g_klo);
    cudaGetSymbolAddress((void**)&gvt,   g_vt2);

    // Fused weight transpose + fp16 pack, one launch for all 3 weights.
    dim3 tgrid(DDIM/32, DDIM/32, 3), tblk(32, 8);
    transpose_pack_kernel<<<tgrid, tblk>>>(
        Wq, Wk, Wv,
        gwt16 + 0*DDIM*DDIM/2, gwt16 + 1*DDIM*DDIM/2, gwt16 + 2*DDIM*DDIM/2);

    // Inputs -> packed fp16, single launch.
    const size_t NA = (size_t)BNUM*SLEN*DDIM;
    const int na4 = (int)(NA/4);
    cvt_f16_kernel<<<dim3((na4+255)/256, 3), 256>>>(
        (const float4*)q, (const float4*)k, (const float4*)v,
        (uint2*)(gaf16 + 0*NA/2), (uint2*)(gaf16 + 1*NA/2), (uint2*)(gaf16 + 2*NA/2), na4);

    // Projections (known-good R10).
    const int proj_smem = 2 * 2 * 128 * PPD * 4;  // 40960
    cudaFuncSetAttribute(proj_mma_kernel,
        cudaFuncAttributeMaxDynamicSharedMemorySize, proj_smem);
    dim3 pgrid(DDIM/128, (BNUM*SLEN)/128, 3);
    proj_mma_kernel<<<pgrid, 256, proj_smem>>>(
        gaf16 + 0*NA/2, gaf16 + 1*NA/2, gaf16 + 2*NA/2,
        gwt16 + 0*DDIM*DDIM/2, gwt16 + 1*DDIM*DDIM/2, gwt16 + 2*DDIM*DDIM/2,
        bq, bk, bv,
        gq, gk, gv);

    // Attention pre-passes.
    const int nw = BNUM*HNUM*SLEN*DKQ/2;
    split_qk_kernel<<<dim3((nw+255)/256, 2), 256>>>(
        (const float2*)gq, (const float2*)gk, gqh, gql, gkh, gkl, nw);
    vt_kernel<<<dim3(BNUM*HNUM, SLEN/64), 128>>>(gv, gvt);

    // Attention (P in registers; smem 73728 B).
    const int attn_smem = 18432 * 4;              // 73728
    cudaFuncSetAttribute(attn_mma_kernel,
        cudaFuncAttributeMaxDynamicSharedMemorySize, attn_smem);
    attn_mma_kernel<<<dim3(BNUM*HNUM, SLEN/64), 128, attn_smem>>>(
        gqh, gql, gkh, gkl, gvt, out);
}

// round 13
// speedup vs baseline: 1.2743x; 1.0367x over previous
#include <cuda_runtime.h>
#include <cuda_bf16.h>
#include <cuda_fp16.h>
#include <cstdint>

#define BNUM 2
#define SLEN 2048
#define DDIM 1024
#define HNUM 16
#define DKQ  64
#define WPD  36     // attn word pitch: 32 data words + 4 pad (banks 4*lr+lc)
#define PPD  20     // proj word pitch: 16 data words + 4 pad

// fp32 V proj output (for vt pass); Q/K go straight to packed bf16.
__device__ float    g_v[BNUM*HNUM*SLEN*DKQ];
__device__ uint32_t g_wt16[3][DDIM*DDIM/2];          // packed fp16 Wt[n][k]
__device__ uint32_t g_af16[3][BNUM*SLEN*DDIM/2];     // packed fp16 inputs
// attention-ready tiles
__device__ uint32_t g_qhi[BNUM*HNUM*SLEN*DKQ/2];     // bf16x2 hi, Q*0.125
__device__ uint32_t g_qlo[BNUM*HNUM*SLEN*DKQ/2];
__device__ uint32_t g_khi[BNUM*HNUM*SLEN*DKQ/2];
__device__ uint32_t g_klo[BNUM*HNUM*SLEN*DKQ/2];
__device__ uint32_t g_vt2[BNUM*HNUM*DKQ*SLEN/2];     // fp16x2 [bh][d][s_pair]

// ---------------- helpers ----------------
__device__ __forceinline__ uint32_t smem_u32(const void* p) {
    uint32_t a;
    asm("{ .reg .u64 t; cvta.to.shared.u64 t, %1; cvt.u32.u64 %0, t; }"
        : "=r"(a) : "l"(p));
    return a;
}
__device__ __forceinline__ void cp16(uint32_t dst, const void* src) {
    asm volatile("cp.async.cg.shared.global [%0], [%1], 16;"
                 :: "r"(dst), "l"(src));
}
#define CP_COMMIT() asm volatile("cp.async.commit_group;" ::: "memory")
#define CP_WAIT1()  asm volatile("cp.async.wait_group 1;" ::: "memory")
#define CP_WAIT0()  asm volatile("cp.async.wait_group 0;" ::: "memory")

__device__ __forceinline__ void mma_bf16(
    float& d0, float& d1, float& d2, float& d3,
    uint32_t a0, uint32_t a1, uint32_t a2, uint32_t a3,
    uint32_t b0, uint32_t b1)
{
    asm volatile(
        "mma.sync.aligned.m16n8k16.row.col.f32.bf16.bf16.f32 "
        "{%0,%1,%2,%3}, {%4,%5,%6,%7}, {%8,%9}, {%0,%1,%2,%3};"
        : "+f"(d0), "+f"(d1), "+f"(d2), "+f"(d3)
        : "r"(a0), "r"(a1), "r"(a2), "r"(a3), "r"(b0), "r"(b1));
}
__device__ __forceinline__ void mma_fp16(
    float& d0, float& d1, float& d2, float& d3,
    uint32_t a0, uint32_t a1, uint32_t a2, uint32_t a3,
    uint32_t b0, uint32_t b1)
{
    asm volatile(
        "mma.sync.aligned.m16n8k16.row.col.f32.f16.f16.f32 "
        "{%0,%1,%2,%3}, {%4,%5,%6,%7}, {%8,%9}, {%0,%1,%2,%3};"
        : "+f"(d0), "+f"(d1), "+f"(d2), "+f"(d3)
        : "r"(a0), "r"(a1), "r"(a2), "r"(a3), "r"(b0), "r"(b1));
}
__device__ __forceinline__ void split_pack_bf16(
    float x0, float x1, uint32_t& whi, uint32_t& wlo)
{
    __nv_bfloat16 h0 = __float2bfloat16(x0);
    __nv_bfloat16 h1 = __float2bfloat16(x1);
    float r0 = x0 - __bfloat162float(h0);
    float r1 = x1 - __bfloat162float(h1);
    __nv_bfloat16 l0 = __float2bfloat16(r0);
    __nv_bfloat16 l1 = __float2bfloat16(r1);
    whi = (uint32_t)__bfloat16_as_ushort(h0) |
          ((uint32_t)__bfloat16_as_ushort(h1) << 16);
    wlo = (uint32_t)__bfloat16_as_ushort(l0) |
          ((uint32_t)__bfloat16_as_ushort(l1) << 16);
}
__device__ __forceinline__ uint32_t pack_h2(float a, float b) {
    __half2 h = __floats2half2_rn(a, b);
    return *(uint32_t*)&h;
}

// ---------------- pre-pass: inputs fp32 -> packed fp16 (3 arrays via y) ----------------
__global__ __launch_bounds__(256) void cvt_f16_kernel(
    const float4* __restrict__ q, const float4* __restrict__ k,
    const float4* __restrict__ v,
    uint2* __restrict__ oq, uint2* __restrict__ ok, uint2* __restrict__ ov, int n4)
{
    int i = blockIdx.x * blockDim.x + threadIdx.x;
    if (i >= n4) return;
    const float4* in = (blockIdx.y == 0) ? q : (blockIdx.y == 1) ? k : v;
    uint2* out       = (blockIdx.y == 0) ? oq : (blockIdx.y == 1) ? ok : ov;
    float4 x = in[i];
    uint2 o = { pack_h2(x.x, x.y), pack_h2(x.z, x.w) };
    out[i] = o;
}

// ---------------- fused weight transpose + fp16 pack, 3 weights via z ----------------
__global__ __launch_bounds__(256) void transpose_pack_kernel(
    const float* __restrict__ w0, const float* __restrict__ w1, const float* __restrict__ w2,
    uint32_t* __restrict__ o0, uint32_t* __restrict__ o1, uint32_t* __restrict__ o2)
{
    __shared__ float t[32][33];
    const float* in = (blockIdx.z == 0) ? w0 : (blockIdx.z == 1) ? w1 : w2;
    uint32_t* out   = (blockIdx.z == 0) ? o0 : (blockIdx.z == 1) ? o1 : o2;
    const int tx = threadIdx.x, ty = threadIdx.y;
    int x = blockIdx.x*32 + tx;
    int y0 = blockIdx.y*32;
#pragma unroll
    for (int j = 0; j < 32; j += 8)
        t[ty + j][tx] = in[(size_t)(y0 + ty + j)*DDIM + x];
    __syncthreads();
    const int tid = ty * 32 + tx;
#pragma unroll
    for (int i = 0; i < 2; i++) {
        int idx = tid + i * 256;          // 0..511 = 32 rows x 16 words
        int row = idx >> 4, wrd = idx & 15;
        uint32_t w = pack_h2(t[2*wrd][row], t[2*wrd + 1][row]);
        out[(size_t)(blockIdx.x*32 + row)*(DDIM/2) + blockIdx.y*16 + wrd] = w;
    }
}

// ---------------- pre-pass: V -> packed fp16x2 transposed [bh][d][s_pair] ----------------
__global__ __launch_bounds__(128) void vt_kernel(
    const float* __restrict__ V, uint32_t* __restrict__ vt2)
{
    __shared__ float sm[64*68];
    const int tid = threadIdx.x;
    const int bh  = blockIdx.x;
    const int st  = blockIdx.y;          // 64-key tile
    const float* Vb = V + ((size_t)bh * SLEN + (size_t)st * 64) * DKQ;
#pragma unroll
    for (int it = 0; it < 8; it++) {
        int f = tid + it * 128;
        int rv = f & 63, cv = (f >> 6) << 2;
        float4 vv = *(const float4*)(Vb + rv * DKQ + cv);
        sm[(cv+0)*68 + rv] = vv.x;
        sm[(cv+1)*68 + rv] = vv.y;
        sm[(cv+2)*68 + rv] = vv.z;
        sm[(cv+3)*68 + rv] = vv.w;
    }
    __syncthreads();
#pragma unroll
    for (int it = 0; it < 16; it++) {
        int f = tid + it * 128;          // 0..2047 = 64 d x 32 words
        int d = f >> 5, sw = f & 31;
        uint32_t w = pack_h2(sm[d*68 + 2*sw], sm[d*68 + 2*sw + 1]);
        vt2[((size_t)bh * DKQ + d) * (SLEN/2) + st * 32 + sw] = w;
    }
}

// ---------------- fp16 HMMA projection; epilogue emits attn-ready formats ----------------
// z=0: Q -> scale 0.125, split bf16 hi/lo packed. z=1: K -> split packed.
// z=2: V -> fp32 [bh][s][dk].
__global__ __launch_bounds__(256, 2) void proj_mma_kernel(
    const uint32_t* __restrict__ A0, const uint32_t* __restrict__ A1, const uint32_t* __restrict__ A2,
    const uint32_t* __restrict__ W0, const uint32_t* __restrict__ W1, const uint32_t* __restrict__ W2,
    const float* __restrict__ bias0, const float* __restrict__ bias1, const float* __restrict__ bias2,
    uint32_t* __restrict__ qhi, uint32_t* __restrict__ qlo,
    uint32_t* __restrict__ khi, uint32_t* __restrict__ klo,
    float* __restrict__ vout)
{
    extern __shared__ uint32_t psm[];        // As[2][128][PPD] | Bs[2][128][PPD]
    uint32_t* As = psm;
    uint32_t* Bs = psm + 2*128*PPD;
    const uint32_t as_u = smem_u32(As);
    const uint32_t bs_u = smem_u32(Bs);

    const int z = blockIdx.z;
    const uint32_t* A  = (z == 0) ? A0 : (z == 1) ? A1 : A2;
    const uint32_t* Wt = (z == 0) ? W0 : (z == 1) ? W1 : W2;
    const float* bias  = (z == 0) ? bias0 : (z == 1) ? bias1 : bias2;

    const int tid  = threadIdx.x;
    const int wid  = tid >> 5;
    const int lane = tid & 31;
    const int lr   = lane >> 2;
    const int lc   = lane & 3;
    const int wm   = (wid >> 2) * 64;
    const int wn   = (wid & 3) * 32;
    const int col0 = blockIdx.x << 7;
    const int row0 = blockIdx.y << 7;

    const uint32_t* Abase = A  + (size_t)row0 * (DDIM/2);
    const uint32_t* Bbase = Wt + (size_t)col0 * (DDIM/2);

    auto issue = [&](int c, int s) {
#pragma unroll
        for (int it = 0; it < 2; it++) {
            int f = tid + it * 256;          // 0..511 : 128 rows x 4 cp16
            int r = f >> 2;
            int o = (f & 3) * 16;            // byte offset within 64B row
            uint32_t d = (uint32_t)((s*128 + r) * (PPD*4)) + o;
            cp16(as_u + d, (const char*)(Abase + (size_t)r * (DDIM/2) + c*16) + o);
            cp16(bs_u + d, (const char*)(Bbase + (size_t)r * (DDIM/2) + c*16) + o);
        }
    };

    float acc[4][4][4];
#pragma unroll
    for (int mt = 0; mt < 4; mt++)
#pragma unroll
        for (int nt = 0; nt < 4; nt++)
#pragma unroll
            for (int i = 0; i < 4; i++) acc[mt][nt][i] = 0.f;

    issue(0, 0); CP_COMMIT();

    for (int c = 0; c < 32; c++) {
        const int s = c & 1;
        __syncthreads();
        if (c < 31) { issue(c + 1, s ^ 1); CP_COMMIT(); CP_WAIT1(); }
        else        { CP_WAIT0(); }
        __syncthreads();

        const uint32_t* Ast = As + s*128*PPD;
        const uint32_t* Bst = Bs + s*128*PPD;
#pragma unroll
        for (int ks = 0; ks < 2; ks++) {     // two k16 steps per 32-chunk
            const int k8 = ks * 8;
            uint32_t a[4][4];
#pragma unroll
            for (int mt = 0; mt < 4; mt++) {
                int r = wm + mt * 16 + lr;
                a[mt][0] = Ast[r*PPD + k8 + lc];
                a[mt][1] = Ast[(r+8)*PPD + k8 + lc];
                a[mt][2] = Ast[r*PPD + k8 + lc + 4];
                a[mt][3] = Ast[(r+8)*PPD + k8 + lc + 4];
            }
#pragma unroll
            for (int nt = 0; nt < 4; nt++) {
                int n = wn + nt * 8 + lr;
                uint32_t b0 = Bst[n*PPD + k8 + lc];
                uint32_t b1 = Bst[n*PPD + k8 + lc + 4];
#pragma unroll
                for (int mt = 0; mt < 4; mt++)
                    mma_fp16(acc[mt][nt][0], acc[mt][nt][1],
                             acc[mt][nt][2], acc[mt][nt][3],
                             a[mt][0], a[mt][1], a[mt][2], a[mt][3], b0, b1);
            }
        }
    }

    // Epilogue: z<2 -> packed bf16 hi/lo (split fused); z==2 -> fp32 V.
    uint32_t* ohi = (z == 0) ? qhi : khi;
    uint32_t* olo = (z == 0) ? qlo : klo;
#pragma unroll
    for (int mt = 0; mt < 4; mt++) {
#pragma unroll
        for (int nt = 0; nt < 4; nt++) {
            int col = col0 + wn + nt * 8 + 2 * lc;
            float2 bb = *(const float2*)(bias + col);
            int head = col >> 6;
            int dk   = col & 63;
#pragma unroll
            for (int h = 0; h < 2; h++) {
                int row = row0 + wm + mt * 16 + lr + h * 8;
                int bi  = row >> 11;
                int si  = row & (SLEN - 1);
                float vx = acc[mt][nt][2*h + 0] + bb.x;
                float vy = acc[mt][nt][2*h + 1] + bb.y;
                if (z == 2) {
                    float2 v = { vx, vy };
                    *(float2*)(vout + ((size_t)(bi * HNUM + head) * SLEN + si) * DKQ + dk) = v;
                } else {
                    if (z == 0) { vx *= 0.125f; vy *= 0.125f; }
                    uint32_t whi, wlo;
                    split_pack_bf16(vx, vy, whi, wlo);
                    size_t wi = ((size_t)(bi * HNUM + head) * SLEN + si) * 32 + (dk >> 1);
                    ohi[wi] = whi;
                    olo[wi] = wlo;
                }
            }
        }
    }
}

// ---------------- cp.async flash attention: P in registers, Q hoisted (R12) ----------------
// Smem word offsets: Qh 0 | Ql 2304 | stage s: Kh 4608+6912s, Kl +2304, Vt +4608
__global__ __launch_bounds__(128) void attn_mma_kernel(
    const uint32_t* __restrict__ Qhi_g, const uint32_t* __restrict__ Qlo_g,
    const uint32_t* __restrict__ Khi_g, const uint32_t* __restrict__ Klo_g,
    const uint32_t* __restrict__ Vt_g,  float* __restrict__ out)
{
    extern __shared__ uint32_t sm[];
    uint32_t* Qh = sm;
    uint32_t* Ql = sm + 2304;
    const uint32_t sm_u = smem_u32(sm);

    const int tid  = threadIdx.x;
    const int w    = tid >> 5;
    const int lane = tid & 31;
    const int lr   = lane >> 2;
    const int lc   = lane & 3;
    const int bh   = blockIdx.x;
    const int qt   = (gridDim.y - 1) - blockIdx.y;

    const uint32_t* Qh_src = Qhi_g + ((size_t)bh * SLEN + (size_t)qt * 64) * 32;
    const uint32_t* Ql_src = Qlo_g + ((size_t)bh * SLEN + (size_t)qt * 64) * 32;

    auto issue_kv = [&](int kt, int s) {
        const uint32_t* Kh_s = Khi_g + ((size_t)bh * SLEN + (size_t)kt * 64) * 32;
        const uint32_t* Kl_s = Klo_g + ((size_t)bh * SLEN + (size_t)kt * 64) * 32;
        const uint32_t* Vt_s = Vt_g  + (size_t)bh * DKQ * (SLEN/2) + (size_t)kt * 32;
        const uint32_t kb = sm_u + (uint32_t)(4608 + s*6912) * 4;
#pragma unroll
        for (int it = 0; it < 4; it++) {
            int f = tid + it * 128;          // 0..511 : 64 rows x 8 cp16
            int r = f >> 3;
            int o = (f & 7) * 16;
            uint32_t d = (uint32_t)(r * (WPD*4)) + o;
            cp16(kb + d,            (const char*)(Kh_s + (size_t)r * 32) + o);
            cp16(kb + 2304*4 + d,   (const char*)(Kl_s + (size_t)r * 32) + o);
            cp16(kb + 4608*4 + d,   (const char*)(Vt_s + (size_t)r * (SLEN/2)) + o);
        }
    };

#pragma unroll
    for (int it = 0; it < 4; it++) {
        int f = tid + it * 128;
        int r = f >> 3;
        int o = (f & 7) * 16;
        uint32_t d = (uint32_t)(r * (WPD*4)) + o;
        cp16(sm_u + d,          (const char*)(Qh_src + (size_t)r * 32) + o);
        cp16(sm_u + 2304*4 + d, (const char*)(Ql_src + (size_t)r * 32) + o);
    }
    issue_kv(0, 0);
    CP_COMMIT();

    float accO[8][4];
#pragma unroll
    for (int nf = 0; nf < 8; nf++)
#pragma unroll
        for (int i = 0; i < 4; i++) accO[nf][i] = 0.f;
    float mrow[2] = { -1e30f, -1e30f };
    float lrow[2] = { 0.f, 0.f };

    uint32_t qh_r[4][4], ql_r[4][4];   // Q fragments, kt-invariant
    uint32_t pw[2][8];                 // packed P words = PV A-fragments

    const int qrow0 = qt*64 + w*16 + lr;
    const int qbw   = (w*16 + lr) * WPD;

    for (int kt = 0; kt <= qt; kt++) {
        const int s = kt & 1;
        __syncthreads();
        if (kt < qt) { issue_kv(kt + 1, s ^ 1); CP_COMMIT(); CP_WAIT1(); }
        else         { CP_WAIT0(); }
        __syncthreads();

        if (kt == 0) {
#pragma unroll
            for (int ks = 0; ks < 4; ks++) {
                const int k8 = ks * 8;
                qh_r[ks][0] = Qh[qbw + k8 + lc];
                qh_r[ks][1] = Qh[qbw + 8*WPD + k8 + lc];
                qh_r[ks][2] = Qh[qbw + k8 + lc + 4];
                qh_r[ks][3] = Qh[qbw + 8*WPD + k8 + lc + 4];
                ql_r[ks][0] = Ql[qbw + k8 + lc];
                ql_r[ks][1] = Ql[qbw + 8*WPD + k8 + lc];
                ql_r[ks][2] = Ql[qbw + k8 + lc + 4];
                ql_r[ks][3] = Ql[qbw + 8*WPD + k8 + lc + 4];
            }
        }

        const uint32_t* Khs = sm + 4608 + s*6912;
        const uint32_t* Kls = Khs + 2304;
        const uint32_t* Vts = Khs + 4608;

        float accS[8][4];
#pragma unroll
        for (int nf = 0; nf < 8; nf++)
#pragma unroll
            for (int i = 0; i < 4; i++) accS[nf][i] = 0.f;

#pragma unroll
        for (int ks = 0; ks < 4; ks++) {
            const int k8 = ks * 8;
#pragma unroll
            for (int nf = 0; nf < 8; nf++) {
                int nb = (nf*8 + lr) * WPD + k8 + lc;
                uint32_t bh0 = Khs[nb], bh1 = Khs[nb + 4];
                uint32_t bl0 = Kls[nb], bl1 = Kls[nb + 4];
                mma_bf16(accS[nf][0], accS[nf][1], accS[nf][2], accS[nf][3],
                         qh_r[ks][0], qh_r[ks][1], qh_r[ks][2], qh_r[ks][3], bh0, bh1);
                mma_bf16(accS[nf][0], accS[nf][1], accS[nf][2], accS[nf][3],
                         qh_r[ks][0], qh_r[ks][1], qh_r[ks][2], qh_r[ks][3], bl0, bl1);
                mma_bf16(accS[nf][0], accS[nf][1], accS[nf][2], accS[nf][3],
                         ql_r[ks][0], ql_r[ks][1], ql_r[ks][2], ql_r[ks][3], bh0, bh1);
            }
        }

        if (kt == qt) {
#pragma unroll
            for (int nf = 0; nf < 8; nf++) {
                int gc = kt*64 + nf*8 + 2*lc;
                if (gc     > qrow0)     accS[nf][0] = -1e30f;
                if (gc + 1 > qrow0)     accS[nf][1] = -1e30f;
                if (gc     > qrow0 + 8) accS[nf][2] = -1e30f;
                if (gc + 1 > qrow0 + 8) accS[nf][3] = -1e30f;
            }
        }

#pragma unroll
        for (int h = 0; h < 2; h++) {
            const int i0 = 2*h, i1 = 2*h + 1;
            float rmax = accS[0][i0];
#pragma unroll
            for (int nf = 0; nf < 8; nf++) {
                rmax = fmaxf(rmax, accS[nf][i0]);
                rmax = fmaxf(rmax, accS[nf][i1]);
            }
            rmax = fmaxf(rmax, __shfl_xor_sync(0xffffffffu, rmax, 1));
            rmax = fmaxf(rmax, __shfl_xor_sync(0xffffffffu, rmax, 2));
            float mn   = fmaxf(mrow[h], rmax);
            float corr = __expf(mrow[h] - mn);
            mrow[h] = mn;
            float rsum = 0.f;
#pragma unroll
            for (int nf = 0; nf < 8; nf++) {
                float e0 = __expf(accS[nf][i0] - mn);
                float e1 = __expf(accS[nf][i1] - mn);
                __half2 hp = __floats2half2_rn(e0, e1);
                pw[h][nf] = *(uint32_t*)&hp;
                rsum += __low2float(hp) + __high2float(hp);
                accO[nf][i0] *= corr;
                accO[nf][i1] *= corr;
            }
            rsum += __shfl_xor_sync(0xffffffffu, rsum, 1);
            rsum += __shfl_xor_sync(0xffffffffu, rsum, 2);
            lrow[h] = lrow[h] * corr + rsum;
        }

#pragma unroll
        for (int ks = 0; ks < 4; ks++) {
            const int k8 = ks * 8;
            uint32_t a0 = pw[0][2*ks];
            uint32_t a1 = pw[1][2*ks];
            uint32_t a2 = pw[0][2*ks + 1];
            uint32_t a3 = pw[1][2*ks + 1];
#pragma unroll
            for (int nf = 0; nf < 8; nf++) {
                int nb = (nf*8 + lr) * WPD + k8 + lc;
                uint32_t b0 = Vts[nb], b1 = Vts[nb + 4];
                mma_fp16(accO[nf][0], accO[nf][1], accO[nf][2], accO[nf][3],
                         a0, a1, a2, a3, b0, b1);
            }
        }
    }

    const int b = bh >> 4, h = bh & 15;
    const float inv0 = 1.f / lrow[0];
    const float inv1 = 1.f / lrow[1];
    const int s0 = qt*64 + w*16 + lr;
    const int s1 = s0 + 8;
#pragma unroll
    for (int nf = 0; nf < 8; nf++) {
        int col = h*DKQ + nf*8 + 2*lc;
        float2 v0 = { accO[nf][0] * inv0, accO[nf][1] * inv0 };
        float2 v1 = { accO[nf][2] * inv1, accO[nf][3] * inv1 };
        *(float2*)(out + ((size_t)b * SLEN + s0) * DDIM + col) = v0;
        *(float2*)(out + ((size_t)b * SLEN + s1) * DDIM + col) = v1;
    }
}

extern "C" void kernel_launch(void* const* d_in, const int* in_sizes, int n_in,
                              void* d_out, int out_size) {
    const float* q  = (const float*)d_in[0];
    const float* k  = (const float*)d_in[1];
    const float* v  = (const float*)d_in[2];
    const float* Wq = (const float*)d_in[3];
    const float* bq = (const float*)d_in[4];
    const float* Wk = (const float*)d_in[5];
    const float* bk = (const float*)d_in[6];
    const float* Wv = (const float*)d_in[7];
    const float* bv = (const float*)d_in[8];
    float* out = (float*)d_out;

    float *gv;
    uint32_t *gwt16, *gaf16, *gqh, *gql, *gkh, *gkl, *gvt;
    cudaGetSymbolAddress((void**)&gv,    g_v);
    cudaGetSymbolAddress((void**)&gwt16, g_wt16);
    cudaGetSymbolAddress((void**)&gaf16, g_af16);
    cudaGetSymbolAddress((void**)&gqh,   g_qhi);
    cudaGetSymbolAddress((void**)&gql,   g_qlo);
    cudaGetSymbolAddress((void**)&gkh,   g_khi);
    cudaGetSymbolAddress((void**)&gkl,   g_klo);
    cudaGetSymbolAddress((void**)&gvt,   g_vt2);

    // Fused weight transpose + fp16 pack, one launch for all 3 weights.
    dim3 tgrid(DDIM/32, DDIM/32, 3), tblk(32, 8);
    transpose_pack_kernel<<<tgrid, tblk>>>(
        Wq, Wk, Wv,
        gwt16 + 0*DDIM*DDIM/2, gwt16 + 1*DDIM*DDIM/2, gwt16 + 2*DDIM*DDIM/2);

    // Inputs -> packed fp16, single launch.
    const size_t NA = (size_t)BNUM*SLEN*DDIM;
    const int na4 = (int)(NA/4);
    cvt_f16_kernel<<<dim3((na4+255)/256, 3), 256>>>(
        (const float4*)q, (const float4*)k, (const float4*)v,
        (uint2*)(gaf16 + 0*NA/2), (uint2*)(gaf16 + 1*NA/2), (uint2*)(gaf16 + 2*NA/2), na4);

    // Projections; Q/K epilogue emits packed bf16 hi/lo directly.
    const int proj_smem = 2 * 2 * 128 * PPD * 4;  // 40960
    cudaFuncSetAttribute(proj_mma_kernel,
        cudaFuncAttributeMaxDynamicSharedMemorySize, proj_smem);
    dim3 pgrid(DDIM/128, (BNUM*SLEN)/128, 3);
    proj_mma_kernel<<<pgrid, 256, proj_smem>>>(
        gaf16 + 0*NA/2, gaf16 + 1*NA/2, gaf16 + 2*NA/2,
        gwt16 + 0*DDIM*DDIM/2, gwt16 + 1*DDIM*DDIM/2, gwt16 + 2*DDIM*DDIM/2,
        bq, bk, bv,
        gqh, gql, gkh, gkl, gv);

    // V pack-transpose.
    vt_kernel<<<dim3(BNUM*HNUM, SLEN/64), 128>>>(gv, gvt);

    // Attention (known-good R12).
    const int attn_smem = 18432 * 4;              // 73728
    cudaFuncSetAttribute(attn_mma_kernel,
        cudaFuncAttributeMaxDynamicSharedMemorySize, attn_smem);
    attn_mma_kernel<<<dim3(BNUM*HNUM, SLEN/64), 128, attn_smem>>>(
        gqh, gql, gkh, gkl, gvt, out);
}

// round 14
// speedup vs baseline: 1.5253x; 1.1969x over previous
#include <cuda_runtime.h>
#include <cuda_bf16.h>
#include <cuda_fp16.h>
#include <cstdint>

#define BNUM 2
#define SLEN 2048
#define DDIM 1024
#define HNUM 16
#define DKQ  64
#define WPD  36     // attn word pitch: 32 data words + 4 pad (banks 4*lr+lc)
#define PPD  20     // proj word pitch: 16 data words + 4 pad

// fp32 V proj output (for vt pass); Q/K go straight to packed fp16.
__device__ float    g_v[BNUM*HNUM*SLEN*DKQ];
__device__ uint32_t g_wt16[3][DDIM*DDIM/2];          // packed fp16 Wt[n][k]
__device__ uint32_t g_af16[3][BNUM*SLEN*DDIM/2];     // packed fp16 inputs
// attention-ready tiles (all packed fp16x2)
__device__ uint32_t g_qf16[BNUM*HNUM*SLEN*DKQ/2];    // Q*0.125, [bh][s][dk/2]
__device__ uint32_t g_kf16[BNUM*HNUM*SLEN*DKQ/2];    // K,       [bh][s][dk/2]
__device__ uint32_t g_vt2 [BNUM*HNUM*DKQ*SLEN/2];    // V,       [bh][d][s_pair]

// ---------------- helpers ----------------
__device__ __forceinline__ uint32_t smem_u32(const void* p) {
    uint32_t a;
    asm("{ .reg .u64 t; cvta.to.shared.u64 t, %1; cvt.u32.u64 %0, t; }"
        : "=r"(a) : "l"(p));
    return a;
}
__device__ __forceinline__ void cp16(uint32_t dst, const void* src) {
    asm volatile("cp.async.cg.shared.global [%0], [%1], 16;"
                 :: "r"(dst), "l"(src));
}
#define CP_COMMIT() asm volatile("cp.async.commit_group;" ::: "memory")
#define CP_WAIT1()  asm volatile("cp.async.wait_group 1;" ::: "memory")
#define CP_WAIT0()  asm volatile("cp.async.wait_group 0;" ::: "memory")

__device__ __forceinline__ void mma_fp16(
    float& d0, float& d1, float& d2, float& d3,
    uint32_t a0, uint32_t a1, uint32_t a2, uint32_t a3,
    uint32_t b0, uint32_t b1)
{
    asm volatile(
        "mma.sync.aligned.m16n8k16.row.col.f32.f16.f16.f32 "
        "{%0,%1,%2,%3}, {%4,%5,%6,%7}, {%8,%9}, {%0,%1,%2,%3};"
        : "+f"(d0), "+f"(d1), "+f"(d2), "+f"(d3)
        : "r"(a0), "r"(a1), "r"(a2), "r"(a3), "r"(b0), "r"(b1));
}
__device__ __forceinline__ uint32_t pack_h2(float a, float b) {
    __half2 h = __floats2half2_rn(a, b);
    return *(uint32_t*)&h;
}

// ---------------- pre-pass: inputs fp32 -> packed fp16 (3 arrays via y) ----------------
__global__ __launch_bounds__(256) void cvt_f16_kernel(
    const float4* __restrict__ q, const float4* __restrict__ k,
    const float4* __restrict__ v,
    uint2* __restrict__ oq, uint2* __restrict__ ok, uint2* __restrict__ ov, int n4)
{
    int i = blockIdx.x * blockDim.x + threadIdx.x;
    if (i >= n4) return;
    const float4* in = (blockIdx.y == 0) ? q : (blockIdx.y == 1) ? k : v;
    uint2* out       = (blockIdx.y == 0) ? oq : (blockIdx.y == 1) ? ok : ov;
    float4 x = in[i];
    uint2 o = { pack_h2(x.x, x.y), pack_h2(x.z, x.w) };
    out[i] = o;
}

// ---------------- fused weight transpose + fp16 pack, 3 weights via z ----------------
__global__ __launch_bounds__(256) void transpose_pack_kernel(
    const float* __restrict__ w0, const float* __restrict__ w1, const float* __restrict__ w2,
    uint32_t* __restrict__ o0, uint32_t* __restrict__ o1, uint32_t* __restrict__ o2)
{
    __shared__ float t[32][33];
    const float* in = (blockIdx.z == 0) ? w0 : (blockIdx.z == 1) ? w1 : w2;
    uint32_t* out   = (blockIdx.z == 0) ? o0 : (blockIdx.z == 1) ? o1 : o2;
    const int tx = threadIdx.x, ty = threadIdx.y;
    int x = blockIdx.x*32 + tx;
    int y0 = blockIdx.y*32;
#pragma unroll
    for (int j = 0; j < 32; j += 8)
        t[ty + j][tx] = in[(size_t)(y0 + ty + j)*DDIM + x];
    __syncthreads();
    const int tid = ty * 32 + tx;
#pragma unroll
    for (int i = 0; i < 2; i++) {
        int idx = tid + i * 256;          // 0..511 = 32 rows x 16 words
        int row = idx >> 4, wrd = idx & 15;
        uint32_t w = pack_h2(t[2*wrd][row], t[2*wrd + 1][row]);
        out[(size_t)(blockIdx.x*32 + row)*(DDIM/2) + blockIdx.y*16 + wrd] = w;
    }
}

// ---------------- pre-pass: V -> packed fp16x2 transposed [bh][d][s_pair] ----------------
__global__ __launch_bounds__(128) void vt_kernel(
    const float* __restrict__ V, uint32_t* __restrict__ vt2)
{
    __shared__ float sm[64*68];
    const int tid = threadIdx.x;
    const int bh  = blockIdx.x;
    const int st  = blockIdx.y;          // 64-key tile
    const float* Vb = V + ((size_t)bh * SLEN + (size_t)st * 64) * DKQ;
#pragma unroll
    for (int it = 0; it < 8; it++) {
        int f = tid + it * 128;
        int rv = f & 63, cv = (f >> 6) << 2;
        float4 vv = *(const float4*)(Vb + rv * DKQ + cv);
        sm[(cv+0)*68 + rv] = vv.x;
        sm[(cv+1)*68 + rv] = vv.y;
        sm[(cv+2)*68 + rv] = vv.z;
        sm[(cv+3)*68 + rv] = vv.w;
    }
    __syncthreads();
#pragma unroll
    for (int it = 0; it < 16; it++) {
        int f = tid + it * 128;          // 0..2047 = 64 d x 32 words
        int d = f >> 5, sw = f & 31;
        uint32_t w = pack_h2(sm[d*68 + 2*sw], sm[d*68 + 2*sw + 1]);
        vt2[((size_t)bh * DKQ + d) * (SLEN/2) + st * 32 + sw] = w;
    }
}

// ---------------- fp16 HMMA projection; epilogue emits attn-ready formats ----------------
// z=0: Q -> scale 0.125, packed fp16. z=1: K -> packed fp16. z=2: V -> fp32.
__global__ __launch_bounds__(256, 2) void proj_mma_kernel(
    const uint32_t* __restrict__ A0, const uint32_t* __restrict__ A1, const uint32_t* __restrict__ A2,
    const uint32_t* __restrict__ W0, const uint32_t* __restrict__ W1, const uint32_t* __restrict__ W2,
    const float* __restrict__ bias0, const float* __restrict__ bias1, const float* __restrict__ bias2,
    uint32_t* __restrict__ qf, uint32_t* __restrict__ kf,
    float* __restrict__ vout)
{
    extern __shared__ uint32_t psm[];        // As[2][128][PPD] | Bs[2][128][PPD]
    uint32_t* As = psm;
    uint32_t* Bs = psm + 2*128*PPD;
    const uint32_t as_u = smem_u32(As);
    const uint32_t bs_u = smem_u32(Bs);

    const int z = blockIdx.z;
    const uint32_t* A  = (z == 0) ? A0 : (z == 1) ? A1 : A2;
    const uint32_t* Wt = (z == 0) ? W0 : (z == 1) ? W1 : W2;
    const float* bias  = (z == 0) ? bias0 : (z == 1) ? bias1 : bias2;

    const int tid  = threadIdx.x;
    const int wid  = tid >> 5;
    const int lane = tid & 31;
    const int lr   = lane >> 2;
    const int lc   = lane & 3;
    const int wm   = (wid >> 2) * 64;
    const int wn   = (wid & 3) * 32;
    const int col0 = blockIdx.x << 7;
    const int row0 = blockIdx.y << 7;

    const uint32_t* Abase = A  + (size_t)row0 * (DDIM/2);
    const uint32_t* Bbase = Wt + (size_t)col0 * (DDIM/2);

    auto issue = [&](int c, int s) {
#pragma unroll
        for (int it = 0; it < 2; it++) {
            int f = tid + it * 256;          // 0..511 : 128 rows x 4 cp16
            int r = f >> 2;
            int o = (f & 3) * 16;            // byte offset within 64B row
            uint32_t d = (uint32_t)((s*128 + r) * (PPD*4)) + o;
            cp16(as_u + d, (const char*)(Abase + (size_t)r * (DDIM/2) + c*16) + o);
            cp16(bs_u + d, (const char*)(Bbase + (size_t)r * (DDIM/2) + c*16) + o);
        }
    };

    float acc[4][4][4];
#pragma unroll
    for (int mt = 0; mt < 4; mt++)
#pragma unroll
        for (int nt = 0; nt < 4; nt++)
#pragma unroll
            for (int i = 0; i < 4; i++) acc[mt][nt][i] = 0.f;

    issue(0, 0); CP_COMMIT();

    for (int c = 0; c < 32; c++) {
        const int s = c & 1;
        __syncthreads();
        if (c < 31) { issue(c + 1, s ^ 1); CP_COMMIT(); CP_WAIT1(); }
        else        { CP_WAIT0(); }
        __syncthreads();

        const uint32_t* Ast = As + s*128*PPD;
        const uint32_t* Bst = Bs + s*128*PPD;
#pragma unroll
        for (int ks = 0; ks < 2; ks++) {     // two k16 steps per 32-chunk
            const int k8 = ks * 8;
            uint32_t a[4][4];
#pragma unroll
            for (int mt = 0; mt < 4; mt++) {
                int r = wm + mt * 16 + lr;
                a[mt][0] = Ast[r*PPD + k8 + lc];
                a[mt][1] = Ast[(r+8)*PPD + k8 + lc];
                a[mt][2] = Ast[r*PPD + k8 + lc + 4];
                a[mt][3] = Ast[(r+8)*PPD + k8 + lc + 4];
            }
#pragma unroll
            for (int nt = 0; nt < 4; nt++) {
                int n = wn + nt * 8 + lr;
                uint32_t b0 = Bst[n*PPD + k8 + lc];
                uint32_t b1 = Bst[n*PPD + k8 + lc + 4];
#pragma unroll
                for (int mt = 0; mt < 4; mt++)
                    mma_fp16(acc[mt][nt][0], acc[mt][nt][1],
                             acc[mt][nt][2], acc[mt][nt][3],
                             a[mt][0], a[mt][1], a[mt][2], a[mt][3], b0, b1);
            }
        }
    }

    // Epilogue: z<2 -> packed fp16; z==2 -> fp32 V.
    uint32_t* opk = (z == 0) ? qf : kf;
#pragma unroll
    for (int mt = 0; mt < 4; mt++) {
#pragma unroll
        for (int nt = 0; nt < 4; nt++) {
            int col = col0 + wn + nt * 8 + 2 * lc;
            float2 bb = *(const float2*)(bias + col);
            int head = col >> 6;
            int dk   = col & 63;
#pragma unroll
            for (int h = 0; h < 2; h++) {
                int row = row0 + wm + mt * 16 + lr + h * 8;
                int bi  = row >> 11;
                int si  = row & (SLEN - 1);
                float vx = acc[mt][nt][2*h + 0] + bb.x;
                float vy = acc[mt][nt][2*h + 1] + bb.y;
                if (z == 2) {
                    float2 v = { vx, vy };
                    *(float2*)(vout + ((size_t)(bi * HNUM + head) * SLEN + si) * DKQ + dk) = v;
                } else {
                    if (z == 0) { vx *= 0.125f; vy *= 0.125f; }
                    size_t wi = ((size_t)(bi * HNUM + head) * SLEN + si) * 32 + (dk >> 1);
                    opk[wi] = pack_h2(vx, vy);
                }
            }
        }
    }
}

// ---------------- cp.async flash attention: fp16 QK, P in registers ----------------
// Smem word offsets: Qf 0 | stage s: Kf 2304+4608s, Vt +2304. Total 11520 words.
__global__ __launch_bounds__(128) void attn_mma_kernel(
    const uint32_t* __restrict__ Qf_g, const uint32_t* __restrict__ Kf_g,
    const uint32_t* __restrict__ Vt_g,  float* __restrict__ out)
{
    extern __shared__ uint32_t sm[];
    uint32_t* Qf = sm;
    const uint32_t sm_u = smem_u32(sm);

    const int tid  = threadIdx.x;
    const int w    = tid >> 5;
    const int lane = tid & 31;
    const int lr   = lane >> 2;
    const int lc   = lane & 3;
    const int bh   = blockIdx.x;
    const int qt   = (gridDim.y - 1) - blockIdx.y;

    const uint32_t* Qf_src = Qf_g + ((size_t)bh * SLEN + (size_t)qt * 64) * 32;

    auto issue_kv = [&](int kt, int s) {
        const uint32_t* Kf_s = Kf_g + ((size_t)bh * SLEN + (size_t)kt * 64) * 32;
        const uint32_t* Vt_s = Vt_g + (size_t)bh * DKQ * (SLEN/2) + (size_t)kt * 32;
        const uint32_t kb = sm_u + (uint32_t)(2304 + s*4608) * 4;
#pragma unroll
        for (int it = 0; it < 4; it++) {
            int f = tid + it * 128;          // 0..511 : 64 rows x 8 cp16
            int r = f >> 3;
            int o = (f & 7) * 16;
            uint32_t d = (uint32_t)(r * (WPD*4)) + o;
            cp16(kb + d,            (const char*)(Kf_s + (size_t)r * 32) + o);
            cp16(kb + 2304*4 + d,   (const char*)(Vt_s + (size_t)r * (SLEN/2)) + o);
        }
    };

#pragma unroll
    for (int it = 0; it < 4; it++) {
        int f = tid + it * 128;
        int r = f >> 3;
        int o = (f & 7) * 16;
        uint32_t d = (uint32_t)(r * (WPD*4)) + o;
        cp16(sm_u + d, (const char*)(Qf_src + (size_t)r * 32) + o);
    }
    issue_kv(0, 0);
    CP_COMMIT();

    float accO[8][4];
#pragma unroll
    for (int nf = 0; nf < 8; nf++)
#pragma unroll
        for (int i = 0; i < 4; i++) accO[nf][i] = 0.f;
    float mrow[2] = { -1e30f, -1e30f };
    float lrow[2] = { 0.f, 0.f };

    uint32_t qf_r[4][4];               // Q fragments, kt-invariant
    uint32_t pw[2][8];                 // packed P words = PV A-fragments

    const int qrow0 = qt*64 + w*16 + lr;
    const int qbw   = (w*16 + lr) * WPD;

    for (int kt = 0; kt <= qt; kt++) {
        const int s = kt & 1;
        __syncthreads();                     // stage-s^1 readers (kt-1) done
        if (kt < qt) { issue_kv(kt + 1, s ^ 1); CP_COMMIT(); CP_WAIT1(); }
        else         { CP_WAIT0(); }
        __syncthreads();                     // stage s (and Q at kt=0) visible

        if (kt == 0) {
#pragma unroll
            for (int ks = 0; ks < 4; ks++) {
                const int k8 = ks * 8;
                qf_r[ks][0] = Qf[qbw + k8 + lc];
                qf_r[ks][1] = Qf[qbw + 8*WPD + k8 + lc];
                qf_r[ks][2] = Qf[qbw + k8 + lc + 4];
                qf_r[ks][3] = Qf[qbw + 8*WPD + k8 + lc + 4];
            }
        }

        const uint32_t* Kfs = sm + 2304 + s*4608;
        const uint32_t* Vts = Kfs + 2304;

        // ---- scores: fp16 QK^T (single mma per ks/nf) ----
        float accS[8][4];
#pragma unroll
        for (int nf = 0; nf < 8; nf++)
#pragma unroll
            for (int i = 0; i < 4; i++) accS[nf][i] = 0.f;

#pragma unroll
        for (int ks = 0; ks < 4; ks++) {
            const int k8 = ks * 8;
#pragma unroll
            for (int nf = 0; nf < 8; nf++) {
                int nb = (nf*8 + lr) * WPD + k8 + lc;
                uint32_t b0 = Kfs[nb], b1 = Kfs[nb + 4];
                mma_fp16(accS[nf][0], accS[nf][1], accS[nf][2], accS[nf][3],
                         qf_r[ks][0], qf_r[ks][1], qf_r[ks][2], qf_r[ks][3], b0, b1);
            }
        }

        if (kt == qt) {
#pragma unroll
            for (int nf = 0; nf < 8; nf++) {
                int gc = kt*64 + nf*8 + 2*lc;
                if (gc     > qrow0)     accS[nf][0] = -1e30f;
                if (gc + 1 > qrow0)     accS[nf][1] = -1e30f;
                if (gc     > qrow0 + 8) accS[nf][2] = -1e30f;
                if (gc + 1 > qrow0 + 8) accS[nf][3] = -1e30f;
            }
        }

        // ---- online softmax; P kept in registers ----
#pragma unroll
        for (int h = 0; h < 2; h++) {
            const int i0 = 2*h, i1 = 2*h + 1;
            float rmax = accS[0][i0];
#pragma unroll
            for (int nf = 0; nf < 8; nf++) {
                rmax = fmaxf(rmax, accS[nf][i0]);
                rmax = fmaxf(rmax, accS[nf][i1]);
            }
            rmax = fmaxf(rmax, __shfl_xor_sync(0xffffffffu, rmax, 1));
            rmax = fmaxf(rmax, __shfl_xor_sync(0xffffffffu, rmax, 2));
            float mn   = fmaxf(mrow[h], rmax);
            float corr = __expf(mrow[h] - mn);
            mrow[h] = mn;
            float rsum = 0.f;
#pragma unroll
            for (int nf = 0; nf < 8; nf++) {
                float e0 = __expf(accS[nf][i0] - mn);
                float e1 = __expf(accS[nf][i1] - mn);
                __half2 hp = __floats2half2_rn(e0, e1);
                pw[h][nf] = *(uint32_t*)&hp;
                rsum += __low2float(hp) + __high2float(hp);
                accO[nf][i0] *= corr;
                accO[nf][i1] *= corr;
            }
            rsum += __shfl_xor_sync(0xffffffffu, rsum, 1);
            rsum += __shfl_xor_sync(0xffffffffu, rsum, 2);
            lrow[h] = lrow[h] * corr + rsum;
        }

        // ---- accO += P @ V (fp16); A-fragments ARE the pw registers ----
#pragma unroll
        for (int ks = 0; ks < 4; ks++) {
            const int k8 = ks * 8;
            uint32_t a0 = pw[0][2*ks];
            uint32_t a1 = pw[1][2*ks];
            uint32_t a2 = pw[0][2*ks + 1];
            uint32_t a3 = pw[1][2*ks + 1];
#pragma unroll
            for (int nf = 0; nf < 8; nf++) {
                int nb = (nf*8 + lr) * WPD + k8 + lc;
                uint32_t b0 = Vts[nb], b1 = Vts[nb + 4];
                mma_fp16(accO[nf][0], accO[nf][1], accO[nf][2], accO[nf][3],
                         a0, a1, a2, a3, b0, b1);
            }
        }
    }

    // ---- epilogue: out[B,S,D] ----
    const int b = bh >> 4, h = bh & 15;
    const float inv0 = 1.f / lrow[0];
    const float inv1 = 1.f / lrow[1];
    const int s0 = qt*64 + w*16 + lr;
    const int s1 = s0 + 8;
#pragma unroll
    for (int nf = 0; nf < 8; nf++) {
        int col = h*DKQ + nf*8 + 2*lc;
        float2 v0 = { accO[nf][0] * inv0, accO[nf][1] * inv0 };
        float2 v1 = { accO[nf][2] * inv1, accO[nf][3] * inv1 };
        *(float2*)(out + ((size_t)b * SLEN + s0) * DDIM + col) = v0;
        *(float2*)(out + ((size_t)b * SLEN + s1) * DDIM + col) = v1;
    }
}

extern "C" void kernel_launch(void* const* d_in, const int* in_sizes, int n_in,
                              void* d_out, int out_size) {
    const float* q  = (const float*)d_in[0];
    const float* k  = (const float*)d_in[1];
    const float* v  = (const float*)d_in[2];
    const float* Wq = (const float*)d_in[3];
    const float* bq = (const float*)d_in[4];
    const float* Wk = (const float*)d_in[5];
    const float* bk = (const float*)d_in[6];
    const float* Wv = (const float*)d_in[7];
    const float* bv = (const float*)d_in[8];
    float* out = (float*)d_out;

    float *gv;
    uint32_t *gwt16, *gaf16, *gqf, *gkf, *gvt;
    cudaGetSymbolAddress((void**)&gv,    g_v);
    cudaGetSymbolAddress((void**)&gwt16, g_wt16);
    cudaGetSymbolAddress((void**)&gaf16, g_af16);
    cudaGetSymbolAddress((void**)&gqf,   g_qf16);
    cudaGetSymbolAddress((void**)&gkf,   g_kf16);
    cudaGetSymbolAddress((void**)&gvt,   g_vt2);

    // Fused weight transpose + fp16 pack, one launch for all 3 weights.
    dim3 tgrid(DDIM/32, DDIM/32, 3), tblk(32, 8);
    transpose_pack_kernel<<<tgrid, tblk>>>(
        Wq, Wk, Wv,
        gwt16 + 0*DDIM*DDIM/2, gwt16 + 1*DDIM*DDIM/2, gwt16 + 2*DDIM*DDIM/2);

    // Inputs -> packed fp16, single launch.
    const size_t NA = (size_t)BNUM*SLEN*DDIM;
    const int na4 = (int)(NA/4);
    cvt_f16_kernel<<<dim3((na4+255)/256, 3), 256>>>(
        (const float4*)q, (const float4*)k, (const float4*)v,
        (uint2*)(gaf16 + 0*NA/2), (uint2*)(gaf16 + 1*NA/2), (uint2*)(gaf16 + 2*NA/2), na4);

    // Projections; Q/K epilogue emits packed fp16 directly.
    const int proj_smem = 2 * 2 * 128 * PPD * 4;  // 40960
    cudaFuncSetAttribute(proj_mma_kernel,
        cudaFuncAttributeMaxDynamicSharedMemorySize, proj_smem);
    dim3 pgrid(DDIM/128, (BNUM*SLEN)/128, 3);
    proj_mma_kernel<<<pgrid, 256, proj_smem>>>(
        gaf16 + 0*NA/2, gaf16 + 1*NA/2, gaf16 + 2*NA/2,
        gwt16 + 0*DDIM*DDIM/2, gwt16 + 1*DDIM*DDIM/2, gwt16 + 2*DDIM*DDIM/2,
        bq, bk, bv,
        gqf, gkf, gv);

    // V pack-transpose.
    vt_kernel<<<dim3(BNUM*HNUM, SLEN/64), 128>>>(gv, gvt);

    // Attention (fp16 QK, smem 46080 B).
    const int attn_smem = 11520 * 4;              // 46080
    cudaFuncSetAttribute(attn_mma_kernel,
        cudaFuncAttributeMaxDynamicSharedMemorySize, attn_smem);
    attn_mma_kernel<<<dim3(BNUM*HNUM, SLEN/64), 128, attn_smem>>>(
        gqf, gkf, gvt, out);
}

// round 15
// speedup vs baseline: 1.5895x; 1.0421x over previous
#include <cuda_runtime.h>
#include <cuda_bf16.h>
#include <cuda_fp16.h>
#include <cstdint>

#define BNUM 2
#define SLEN 2048
#define DDIM 1024
#define HNUM 16
#define DKQ  64
#define WPD  36     // attn word pitch: 32 data words + 4 pad (banks 4*lr+lc)
#define PPD  20     // proj word pitch: 16 data words + 4 pad

__device__ uint32_t g_wt16[3][DDIM*DDIM/2];          // packed fp16 Wt[n][k]
__device__ uint32_t g_af16[3][BNUM*SLEN*DDIM/2];     // packed fp16 inputs
// attention-ready tiles (all packed fp16x2)
__device__ uint32_t g_qf16[BNUM*HNUM*SLEN*DKQ/2];    // Q*0.125, [bh][s][dk/2]
__device__ uint32_t g_kf16[BNUM*HNUM*SLEN*DKQ/2];    // K,       [bh][s][dk/2]
__device__ uint32_t g_vt2 [BNUM*HNUM*DKQ*SLEN/2];    // V,       [bh][d][s_pair]

// ---------------- helpers ----------------
__device__ __forceinline__ uint32_t smem_u32(const void* p) {
    uint32_t a;
    asm("{ .reg .u64 t; cvta.to.shared.u64 t, %1; cvt.u32.u64 %0, t; }"
        : "=r"(a) : "l"(p));
    return a;
}
__device__ __forceinline__ void cp16(uint32_t dst, const void* src) {
    asm volatile("cp.async.cg.shared.global [%0], [%1], 16;"
                 :: "r"(dst), "l"(src));
}
#define CP_COMMIT() asm volatile("cp.async.commit_group;" ::: "memory")
#define CP_WAIT1()  asm volatile("cp.async.wait_group 1;" ::: "memory")
#define CP_WAIT0()  asm volatile("cp.async.wait_group 0;" ::: "memory")

__device__ __forceinline__ void mma_fp16(
    float& d0, float& d1, float& d2, float& d3,
    uint32_t a0, uint32_t a1, uint32_t a2, uint32_t a3,
    uint32_t b0, uint32_t b1)
{
    asm volatile(
        "mma.sync.aligned.m16n8k16.row.col.f32.f16.f16.f32 "
        "{%0,%1,%2,%3}, {%4,%5,%6,%7}, {%8,%9}, {%0,%1,%2,%3};"
        : "+f"(d0), "+f"(d1), "+f"(d2), "+f"(d3)
        : "r"(a0), "r"(a1), "r"(a2), "r"(a3), "r"(b0), "r"(b1));
}
__device__ __forceinline__ uint32_t pack_h2(float a, float b) {
    __half2 h = __floats2half2_rn(a, b);
    return *(uint32_t*)&h;
}

// ---------------- pre-pass: inputs fp32 -> packed fp16 (3 arrays via y) ----------------
__global__ __launch_bounds__(256) void cvt_f16_kernel(
    const float4* __restrict__ q, const float4* __restrict__ k,
    const float4* __restrict__ v,
    uint2* __restrict__ oq, uint2* __restrict__ ok, uint2* __restrict__ ov, int n4)
{
    int i = blockIdx.x * blockDim.x + threadIdx.x;
    if (i >= n4) return;
    const float4* in = (blockIdx.y == 0) ? q : (blockIdx.y == 1) ? k : v;
    uint2* out       = (blockIdx.y == 0) ? oq : (blockIdx.y == 1) ? ok : ov;
    float4 x = in[i];
    uint2 o = { pack_h2(x.x, x.y), pack_h2(x.z, x.w) };
    out[i] = o;
}

// ---------------- fused weight transpose + fp16 pack, 3 weights via z ----------------
__global__ __launch_bounds__(256) void transpose_pack_kernel(
    const float* __restrict__ w0, const float* __restrict__ w1, const float* __restrict__ w2,
    uint32_t* __restrict__ o0, uint32_t* __restrict__ o1, uint32_t* __restrict__ o2)
{
    __shared__ float t[32][33];
    const float* in = (blockIdx.z == 0) ? w0 : (blockIdx.z == 1) ? w1 : w2;
    uint32_t* out   = (blockIdx.z == 0) ? o0 : (blockIdx.z == 1) ? o1 : o2;
    const int tx = threadIdx.x, ty = threadIdx.y;
    int x = blockIdx.x*32 + tx;
    int y0 = blockIdx.y*32;
#pragma unroll
    for (int j = 0; j < 32; j += 8)
        t[ty + j][tx] = in[(size_t)(y0 + ty + j)*DDIM + x];
    __syncthreads();
    const int tid = ty * 32 + tx;
#pragma unroll
    for (int i = 0; i < 2; i++) {
        int idx = tid + i * 256;          // 0..511 = 32 rows x 16 words
        int row = idx >> 4, wrd = idx & 15;
        uint32_t w = pack_h2(t[2*wrd][row], t[2*wrd + 1][row]);
        out[(size_t)(blockIdx.x*32 + row)*(DDIM/2) + blockIdx.y*16 + wrd] = w;
    }
}

// ---------------- fp16 HMMA projection; epilogue emits attn-ready formats ----------------
// z=0: Q -> scale 0.125, packed fp16 [bh][s][dk/2].
// z=1: K -> packed fp16 [bh][s][dk/2].
// z=2: V -> packed fp16x2 TRANSPOSED [bh][d][s_pair] (shuffle-paired in epilogue).
__global__ __launch_bounds__(256, 2) void proj_mma_kernel(
    const uint32_t* __restrict__ A0, const uint32_t* __restrict__ A1, const uint32_t* __restrict__ A2,
    const uint32_t* __restrict__ W0, const uint32_t* __restrict__ W1, const uint32_t* __restrict__ W2,
    const float* __restrict__ bias0, const float* __restrict__ bias1, const float* __restrict__ bias2,
    uint32_t* __restrict__ qf, uint32_t* __restrict__ kf,
    uint32_t* __restrict__ vt2)
{
    extern __shared__ uint32_t psm[];        // As[2][128][PPD] | Bs[2][128][PPD]
    uint32_t* As = psm;
    uint32_t* Bs = psm + 2*128*PPD;
    const uint32_t as_u = smem_u32(As);
    const uint32_t bs_u = smem_u32(Bs);

    const int z = blockIdx.z;
    const uint32_t* A  = (z == 0) ? A0 : (z == 1) ? A1 : A2;
    const uint32_t* Wt = (z == 0) ? W0 : (z == 1) ? W1 : W2;
    const float* bias  = (z == 0) ? bias0 : (z == 1) ? bias1 : bias2;

    const int tid  = threadIdx.x;
    const int wid  = tid >> 5;
    const int lane = tid & 31;
    const int lr   = lane >> 2;
    const int lc   = lane & 3;
    const int wm   = (wid >> 2) * 64;
    const int wn   = (wid & 3) * 32;
    const int col0 = blockIdx.x << 7;
    const int row0 = blockIdx.y << 7;

    const uint32_t* Abase = A  + (size_t)row0 * (DDIM/2);
    const uint32_t* Bbase = Wt + (size_t)col0 * (DDIM/2);

    auto issue = [&](int c, int s) {
#pragma unroll
        for (int it = 0; it < 2; it++) {
            int f = tid + it * 256;          // 0..511 : 128 rows x 4 cp16
            int r = f >> 2;
            int o = (f & 3) * 16;            // byte offset within 64B row
            uint32_t d = (uint32_t)((s*128 + r) * (PPD*4)) + o;
            cp16(as_u + d, (const char*)(Abase + (size_t)r * (DDIM/2) + c*16) + o);
            cp16(bs_u + d, (const char*)(Bbase + (size_t)r * (DDIM/2) + c*16) + o);
        }
    };

    float acc[4][4][4];
#pragma unroll
    for (int mt = 0; mt < 4; mt++)
#pragma unroll
        for (int nt = 0; nt < 4; nt++)
#pragma unroll
            for (int i = 0; i < 4; i++) acc[mt][nt][i] = 0.f;

    issue(0, 0); CP_COMMIT();

    for (int c = 0; c < 32; c++) {
        const int s = c & 1;
        __syncthreads();
        if (c < 31) { issue(c + 1, s ^ 1); CP_COMMIT(); CP_WAIT1(); }
        else        { CP_WAIT0(); }
        __syncthreads();

        const uint32_t* Ast = As + s*128*PPD;
        const uint32_t* Bst = Bs + s*128*PPD;
#pragma unroll
        for (int ks = 0; ks < 2; ks++) {     // two k16 steps per 32-chunk
            const int k8 = ks * 8;
            uint32_t a[4][4];
#pragma unroll
            for (int mt = 0; mt < 4; mt++) {
                int r = wm + mt * 16 + lr;
                a[mt][0] = Ast[r*PPD + k8 + lc];
                a[mt][1] = Ast[(r+8)*PPD + k8 + lc];
                a[mt][2] = Ast[r*PPD + k8 + lc + 4];
                a[mt][3] = Ast[(r+8)*PPD + k8 + lc + 4];
            }
#pragma unroll
            for (int nt = 0; nt < 4; nt++) {
                int n = wn + nt * 8 + lr;
                uint32_t b0 = Bst[n*PPD + k8 + lc];
                uint32_t b1 = Bst[n*PPD + k8 + lc + 4];
#pragma unroll
                for (int mt = 0; mt < 4; mt++)
                    mma_fp16(acc[mt][nt][0], acc[mt][nt][1],
                             acc[mt][nt][2], acc[mt][nt][3],
                             a[mt][0], a[mt][1], a[mt][2], a[mt][3], b0, b1);
            }
        }
    }

    // Epilogue: z<2 -> packed fp16 [bh][s][dk/2]; z==2 -> fp16x2 transposed.
    uint32_t* opk = (z == 0) ? qf : kf;
#pragma unroll
    for (int mt = 0; mt < 4; mt++) {
#pragma unroll
        for (int nt = 0; nt < 4; nt++) {
            int col = col0 + wn + nt * 8 + 2 * lc;
            float2 bb = *(const float2*)(bias + col);
            int head = col >> 6;
            int dk   = col & 63;
#pragma unroll
            for (int h = 0; h < 2; h++) {
                int row = row0 + wm + mt * 16 + lr + h * 8;
                int bi  = row >> 11;
                int si  = row & (SLEN - 1);
                float vx = acc[mt][nt][2*h + 0] + bb.x;
                float vy = acc[mt][nt][2*h + 1] + bb.y;
                if (z == 2) {
                    // Pair s-adjacent rows (lr even/odd <-> lane xor 4), pack,
                    // store transposed [bh][d][s_pair]. Even-lr lanes store.
                    float px = __shfl_xor_sync(0xffffffffu, vx, 4);
                    float py = __shfl_xor_sync(0xffffffffu, vy, 4);
                    if (!(lane & 4)) {
                        size_t base = ((size_t)(bi * HNUM + head) * DKQ + dk) * (SLEN/2);
                        vt2[base + (si >> 1)]            = pack_h2(vx, px);
                        vt2[base + (SLEN/2) + (si >> 1)] = pack_h2(vy, py);
                    }
                } else {
                    if (z == 0) { vx *= 0.125f; vy *= 0.125f; }
                    size_t wi = ((size_t)(bi * HNUM + head) * SLEN + si) * 32 + (dk >> 1);
                    opk[wi] = pack_h2(vx, vy);
                }
            }
        }
    }
}

// ---------------- cp.async flash attention: fp16 QK, P in registers (R14) ----------------
// Smem word offsets: Qf 0 | stage s: Kf 2304+4608s, Vt +2304. Total 11520 words.
__global__ __launch_bounds__(128) void attn_mma_kernel(
    const uint32_t* __restrict__ Qf_g, const uint32_t* __restrict__ Kf_g,
    const uint32_t* __restrict__ Vt_g,  float* __restrict__ out)
{
    extern __shared__ uint32_t sm[];
    uint32_t* Qf = sm;
    const uint32_t sm_u = smem_u32(sm);

    const int tid  = threadIdx.x;
    const int w    = tid >> 5;
    const int lane = tid & 31;
    const int lr   = lane >> 2;
    const int lc   = lane & 3;
    const int bh   = blockIdx.x;
    const int qt   = (gridDim.y - 1) - blockIdx.y;

    const uint32_t* Qf_src = Qf_g + ((size_t)bh * SLEN + (size_t)qt * 64) * 32;

    auto issue_kv = [&](int kt, int s) {
        const uint32_t* Kf_s = Kf_g + ((size_t)bh * SLEN + (size_t)kt * 64) * 32;
        const uint32_t* Vt_s = Vt_g + (size_t)bh * DKQ * (SLEN/2) + (size_t)kt * 32;
        const uint32_t kb = sm_u + (uint32_t)(2304 + s*4608) * 4;
#pragma unroll
        for (int it = 0; it < 4; it++) {
            int f = tid + it * 128;          // 0..511 : 64 rows x 8 cp16
            int r = f >> 3;
            int o = (f & 7) * 16;
            uint32_t d = (uint32_t)(r * (WPD*4)) + o;
            cp16(kb + d,            (const char*)(Kf_s + (size_t)r * 32) + o);
            cp16(kb + 2304*4 + d,   (const char*)(Vt_s + (size_t)r * (SLEN/2)) + o);
        }
    };

#pragma unroll
    for (int it = 0; it < 4; it++) {
        int f = tid + it * 128;
        int r = f >> 3;
        int o = (f & 7) * 16;
        uint32_t d = (uint32_t)(r * (WPD*4)) + o;
        cp16(sm_u + d, (const char*)(Qf_src + (size_t)r * 32) + o);
    }
    issue_kv(0, 0);
    CP_COMMIT();

    float accO[8][4];
#pragma unroll
    for (int nf = 0; nf < 8; nf++)
#pragma unroll
        for (int i = 0; i < 4; i++) accO[nf][i] = 0.f;
    float mrow[2] = { -1e30f, -1e30f };
    float lrow[2] = { 0.f, 0.f };

    uint32_t qf_r[4][4];               // Q fragments, kt-invariant
    uint32_t pw[2][8];                 // packed P words = PV A-fragments

    const int qrow0 = qt*64 + w*16 + lr;
    const int qbw   = (w*16 + lr) * WPD;

    for (int kt = 0; kt <= qt; kt++) {
        const int s = kt & 1;
        __syncthreads();                     // stage-s^1 readers (kt-1) done
        if (kt < qt) { issue_kv(kt + 1, s ^ 1); CP_COMMIT(); CP_WAIT1(); }
        else         { CP_WAIT0(); }
        __syncthreads();                     // stage s (and Q at kt=0) visible

        if (kt == 0) {
#pragma unroll
            for (int ks = 0; ks < 4; ks++) {
                const int k8 = ks * 8;
                qf_r[ks][0] = Qf[qbw + k8 + lc];
                qf_r[ks][1] = Qf[qbw + 8*WPD + k8 + lc];
                qf_r[ks][2] = Qf[qbw + k8 + lc + 4];
                qf_r[ks][3] = Qf[qbw + 8*WPD + k8 + lc + 4];
            }
        }

        const uint32_t* Kfs = sm + 2304 + s*4608;
        const uint32_t* Vts = Kfs + 2304;

        // ---- scores: fp16 QK^T ----
        float accS[8][4];
#pragma unroll
        for (int nf = 0; nf < 8; nf++)
#pragma unroll
            for (int i = 0; i < 4; i++) accS[nf][i] = 0.f;

#pragma unroll
        for (int ks = 0; ks < 4; ks++) {
            const int k8 = ks * 8;
#pragma unroll
            for (int nf = 0; nf < 8; nf++) {
                int nb = (nf*8 + lr) * WPD + k8 + lc;
                uint32_t b0 = Kfs[nb], b1 = Kfs[nb + 4];
                mma_fp16(accS[nf][0], accS[nf][1], accS[nf][2], accS[nf][3],
                         qf_r[ks][0], qf_r[ks][1], qf_r[ks][2], qf_r[ks][3], b0, b1);
            }
        }

        if (kt == qt) {
#pragma unroll
            for (int nf = 0; nf < 8; nf++) {
                int gc = kt*64 + nf*8 + 2*lc;
                if (gc     > qrow0)     accS[nf][0] = -1e30f;
                if (gc + 1 > qrow0)     accS[nf][1] = -1e30f;
                if (gc     > qrow0 + 8) accS[nf][2] = -1e30f;
                if (gc + 1 > qrow0 + 8) accS[nf][3] = -1e30f;
            }
        }

        // ---- online softmax; P kept in registers ----
#pragma unroll
        for (int h = 0; h < 2; h++) {
            const int i0 = 2*h, i1 = 2*h + 1;
            float rmax = accS[0][i0];
#pragma unroll
            for (int nf = 0; nf < 8; nf++) {
                rmax = fmaxf(rmax, accS[nf][i0]);
                rmax = fmaxf(rmax, accS[nf][i1]);
            }
            rmax = fmaxf(rmax, __shfl_xor_sync(0xffffffffu, rmax, 1));
            rmax = fmaxf(rmax, __shfl_xor_sync(0xffffffffu, rmax, 2));
            float mn   = fmaxf(mrow[h], rmax);
            float corr = __expf(mrow[h] - mn);
            mrow[h] = mn;
            float rsum = 0.f;
#pragma unroll
            for (int nf = 0; nf < 8; nf++) {
                float e0 = __expf(accS[nf][i0] - mn);
                float e1 = __expf(accS[nf][i1] - mn);
                __half2 hp = __floats2half2_rn(e0, e1);
                pw[h][nf] = *(uint32_t*)&hp;
                rsum += __low2float(hp) + __high2float(hp);
                accO[nf][i0] *= corr;
                accO[nf][i1] *= corr;
            }
            rsum += __shfl_xor_sync(0xffffffffu, rsum, 1);
            rsum += __shfl_xor_sync(0xffffffffu, rsum, 2);
            lrow[h] = lrow[h] * corr + rsum;
        }

        // ---- accO += P @ V (fp16); A-fragments ARE the pw registers ----
#pragma unroll
        for (int ks = 0; ks < 4; ks++) {
            const int k8 = ks * 8;
            uint32_t a0 = pw[0][2*ks];
            uint32_t a1 = pw[1][2*ks];
            uint32_t a2 = pw[0][2*ks + 1];
            uint32_t a3 = pw[1][2*ks + 1];
#pragma unroll
            for (int nf = 0; nf < 8; nf++) {
                int nb = (nf*8 + lr) * WPD + k8 + lc;
                uint32_t b0 = Vts[nb], b1 = Vts[nb + 4];
                mma_fp16(accO[nf][0], accO[nf][1], accO[nf][2], accO[nf][3],
                         a0, a1, a2, a3, b0, b1);
            }
        }
    }

    // ---- epilogue: out[B,S,D] ----
    const int b = bh >> 4, h = bh & 15;
    const float inv0 = 1.f / lrow[0];
    const float inv1 = 1.f / lrow[1];
    const int s0 = qt*64 + w*16 + lr;
    const int s1 = s0 + 8;
#pragma unroll
    for (int nf = 0; nf < 8; nf++) {
        int col = h*DKQ + nf*8 + 2*lc;
        float2 v0 = { accO[nf][0] * inv0, accO[nf][1] * inv0 };
        float2 v1 = { accO[nf][2] * inv1, accO[nf][3] * inv1 };
        *(float2*)(out + ((size_t)b * SLEN + s0) * DDIM + col) = v0;
        *(float2*)(out + ((size_t)b * SLEN + s1) * DDIM + col) = v1;
    }
}

extern "C" void kernel_launch(void* const* d_in, const int* in_sizes, int n_in,
                              void* d_out, int out_size) {
    const float* q  = (const float*)d_in[0];
    const float* k  = (const float*)d_in[1];
    const float* v  = (const float*)d_in[2];
    const float* Wq = (const float*)d_in[3];
    const float* bq = (const float*)d_in[4];
    const float* Wk = (const float*)d_in[5];
    const float* bk = (const float*)d_in[6];
    const float* Wv = (const float*)d_in[7];
    const float* bv = (const float*)d_in[8];
    float* out = (float*)d_out;

    uint32_t *gwt16, *gaf16, *gqf, *gkf, *gvt;
    cudaGetSymbolAddress((void**)&gwt16, g_wt16);
    cudaGetSymbolAddress((void**)&gaf16, g_af16);
    cudaGetSymbolAddress((void**)&gqf,   g_qf16);
    cudaGetSymbolAddress((void**)&gkf,   g_kf16);
    cudaGetSymbolAddress((void**)&gvt,   g_vt2);

    // Fused weight transpose + fp16 pack, one launch for all 3 weights.
    dim3 tgrid(DDIM/32, DDIM/32, 3), tblk(32, 8);
    transpose_pack_kernel<<<tgrid, tblk>>>(
        Wq, Wk, Wv,
        gwt16 + 0*DDIM*DDIM/2, gwt16 + 1*DDIM*DDIM/2, gwt16 + 2*DDIM*DDIM/2);

    // Inputs -> packed fp16, single launch.
    const size_t NA = (size_t)BNUM*SLEN*DDIM;
    const int na4 = (int)(NA/4);
    cvt_f16_kernel<<<dim3((na4+255)/256, 3), 256>>>(
        (const float4*)q, (const float4*)k, (const float4*)v,
        (uint2*)(gaf16 + 0*NA/2), (uint2*)(gaf16 + 1*NA/2), (uint2*)(gaf16 + 2*NA/2), na4);

    // Projections; epilogue emits packed fp16 Q/K and transposed fp16 V directly.
    const int proj_smem = 2 * 2 * 128 * PPD * 4;  // 40960
    cudaFuncSetAttribute(proj_mma_kernel,
        cudaFuncAttributeMaxDynamicSharedMemorySize, proj_smem);
    dim3 pgrid(DDIM/128, (BNUM*SLEN)/128, 3);
    proj_mma_kernel<<<pgrid, 256, proj_smem>>>(
        gaf16 + 0*NA/2, gaf16 + 1*NA/2, gaf16 + 2*NA/2,
        gwt16 + 0*DDIM*DDIM/2, gwt16 + 1*DDIM*DDIM/2, gwt16 + 2*DDIM*DDIM/2,
        bq, bk, bv,
        gqf, gkf, gvt);

    // Attention (fp16 QK, smem 46080 B).
    const int attn_smem = 11520 * 4;              // 46080
    cudaFuncSetAttribute(attn_mma_kernel,
        cudaFuncAttributeMaxDynamicSharedMemorySize, attn_smem);
    attn_mma_kernel<<<dim3(BNUM*HNUM, SLEN/64), 128, attn_smem>>>(
        gqf, gkf, gvt, out);
}

// round 16
// speedup vs baseline: 1.7334x; 1.0905x over previous
#include <cuda_runtime.h>
#include <cuda_bf16.h>
#include <cuda_fp16.h>
#include <cstdint>

#define BNUM 2
#define SLEN 2048
#define DDIM 1024
#define HNUM 16
#define DKQ  64
#define WPD  36     // word pitch for 32-data-word rows (+4 pad): banks 4*lr+lc, conflict-free

__device__ uint32_t g_wt16[3][DDIM*DDIM/2];          // packed fp16 Wt[n][k]
__device__ uint32_t g_af16[3][BNUM*SLEN*DDIM/2];     // packed fp16 inputs
// attention-ready tiles (all packed fp16x2)
__device__ uint32_t g_qf16[BNUM*HNUM*SLEN*DKQ/2];    // Q*0.125, [bh][s][dk/2]
__device__ uint32_t g_kf16[BNUM*HNUM*SLEN*DKQ/2];    // K,       [bh][s][dk/2]
__device__ uint32_t g_vt2 [BNUM*HNUM*DKQ*SLEN/2];    // V,       [bh][d][s_pair]

// ---------------- helpers ----------------
__device__ __forceinline__ uint32_t smem_u32(const void* p) {
    uint32_t a;
    asm("{ .reg .u64 t; cvta.to.shared.u64 t, %1; cvt.u32.u64 %0, t; }"
        : "=r"(a) : "l"(p));
    return a;
}
__device__ __forceinline__ void cp16(uint32_t dst, const void* src) {
    asm volatile("cp.async.cg.shared.global [%0], [%1], 16;"
                 :: "r"(dst), "l"(src));
}
#define CP_COMMIT() asm volatile("cp.async.commit_group;" ::: "memory")
#define CP_WAIT1()  asm volatile("cp.async.wait_group 1;" ::: "memory")
#define CP_WAIT0()  asm volatile("cp.async.wait_group 0;" ::: "memory")

__device__ __forceinline__ void mma_fp16(
    float& d0, float& d1, float& d2, float& d3,
    uint32_t a0, uint32_t a1, uint32_t a2, uint32_t a3,
    uint32_t b0, uint32_t b1)
{
    asm volatile(
        "mma.sync.aligned.m16n8k16.row.col.f32.f16.f16.f32 "
        "{%0,%1,%2,%3}, {%4,%5,%6,%7}, {%8,%9}, {%0,%1,%2,%3};"
        : "+f"(d0), "+f"(d1), "+f"(d2), "+f"(d3)
        : "r"(a0), "r"(a1), "r"(a2), "r"(a3), "r"(b0), "r"(b1));
}
__device__ __forceinline__ uint32_t pack_h2(float a, float b) {
    __half2 h = __floats2half2_rn(a, b);
    return *(uint32_t*)&h;
}

// ---------------- pre-pass: inputs fp32 -> packed fp16 (3 arrays via y) ----------------
__global__ __launch_bounds__(256) void cvt_f16_kernel(
    const float4* __restrict__ q, const float4* __restrict__ k,
    const float4* __restrict__ v,
    uint2* __restrict__ oq, uint2* __restrict__ ok, uint2* __restrict__ ov, int n4)
{
    int i = blockIdx.x * blockDim.x + threadIdx.x;
    if (i >= n4) return;
    const float4* in = (blockIdx.y == 0) ? q : (blockIdx.y == 1) ? k : v;
    uint2* out       = (blockIdx.y == 0) ? oq : (blockIdx.y == 1) ? ok : ov;
    float4 x = in[i];
    uint2 o = { pack_h2(x.x, x.y), pack_h2(x.z, x.w) };
    out[i] = o;
}

// ---------------- fused weight transpose + fp16 pack, 3 weights via z ----------------
__global__ __launch_bounds__(256) void transpose_pack_kernel(
    const float* __restrict__ w0, const float* __restrict__ w1, const float* __restrict__ w2,
    uint32_t* __restrict__ o0, uint32_t* __restrict__ o1, uint32_t* __restrict__ o2)
{
    __shared__ float t[32][33];
    const float* in = (blockIdx.z == 0) ? w0 : (blockIdx.z == 1) ? w1 : w2;
    uint32_t* out   = (blockIdx.z == 0) ? o0 : (blockIdx.z == 1) ? o1 : o2;
    const int tx = threadIdx.x, ty = threadIdx.y;
    int x = blockIdx.x*32 + tx;
    int y0 = blockIdx.y*32;
#pragma unroll
    for (int j = 0; j < 32; j += 8)
        t[ty + j][tx] = in[(size_t)(y0 + ty + j)*DDIM + x];
    __syncthreads();
    const int tid = ty * 32 + tx;
#pragma unroll
    for (int i = 0; i < 2; i++) {
        int idx = tid + i * 256;          // 0..511 = 32 rows x 16 words
        int row = idx >> 4, wrd = idx & 15;
        uint32_t w = pack_h2(t[2*wrd][row], t[2*wrd + 1][row]);
        out[(size_t)(blockIdx.x*32 + row)*(DDIM/2) + blockIdx.y*16 + wrd] = w;
    }
}

// ---------------- fp16 HMMA projection, K-chunk 64, epilogue emits attn formats ----------------
// z=0: Q -> scale 0.125, packed fp16 [bh][s][dk/2].
// z=1: K -> packed fp16 [bh][s][dk/2].
// z=2: V -> packed fp16x2 TRANSPOSED [bh][d][s_pair] (shuffle-paired in epilogue).
__global__ __launch_bounds__(256, 2) void proj_mma_kernel(
    const uint32_t* __restrict__ A0, const uint32_t* __restrict__ A1, const uint32_t* __restrict__ A2,
    const uint32_t* __restrict__ W0, const uint32_t* __restrict__ W1, const uint32_t* __restrict__ W2,
    const float* __restrict__ bias0, const float* __restrict__ bias1, const float* __restrict__ bias2,
    uint32_t* __restrict__ qf, uint32_t* __restrict__ kf,
    uint32_t* __restrict__ vt2)
{
    extern __shared__ uint32_t psm[];        // As[2][128][WPD] | Bs[2][128][WPD]
    uint32_t* As = psm;
    uint32_t* Bs = psm + 2*128*WPD;
    const uint32_t as_u = smem_u32(As);
    const uint32_t bs_u = smem_u32(Bs);

    const int z = blockIdx.z;
    const uint32_t* A  = (z == 0) ? A0 : (z == 1) ? A1 : A2;
    const uint32_t* Wt = (z == 0) ? W0 : (z == 1) ? W1 : W2;
    const float* bias  = (z == 0) ? bias0 : (z == 1) ? bias1 : bias2;

    const int tid  = threadIdx.x;
    const int wid  = tid >> 5;
    const int lane = tid & 31;
    const int lr   = lane >> 2;
    const int lc   = lane & 3;
    const int wm   = (wid >> 2) * 64;
    const int wn   = (wid & 3) * 32;
    const int col0 = blockIdx.x << 7;
    const int row0 = blockIdx.y << 7;

    const uint32_t* Abase = A  + (size_t)row0 * (DDIM/2);
    const uint32_t* Bbase = Wt + (size_t)col0 * (DDIM/2);

    // Load one 64-element K-chunk (32 words per row) of A and B into stage s.
    auto issue = [&](int c, int s) {
#pragma unroll
        for (int it = 0; it < 4; it++) {
            int f = tid + it * 256;          // 0..1023 : 128 rows x 8 cp16
            int r = f >> 3;
            int o = (f & 7) * 16;            // byte offset within 128B row
            uint32_t d = (uint32_t)((s*128 + r) * (WPD*4)) + o;
            cp16(as_u + d, (const char*)(Abase + (size_t)r * (DDIM/2) + c*32) + o);
            cp16(bs_u + d, (const char*)(Bbase + (size_t)r * (DDIM/2) + c*32) + o);
        }
    };

    float acc[4][4][4];
#pragma unroll
    for (int mt = 0; mt < 4; mt++)
#pragma unroll
        for (int nt = 0; nt < 4; nt++)
#pragma unroll
            for (int i = 0; i < 4; i++) acc[mt][nt][i] = 0.f;

    issue(0, 0); CP_COMMIT();

    for (int c = 0; c < 16; c++) {           // 16 K-chunks of 64 fp16
        const int s = c & 1;
        __syncthreads();
        if (c < 15) { issue(c + 1, s ^ 1); CP_COMMIT(); CP_WAIT1(); }
        else        { CP_WAIT0(); }
        __syncthreads();

        const uint32_t* Ast = As + s*128*WPD;
        const uint32_t* Bst = Bs + s*128*WPD;
#pragma unroll
        for (int ks = 0; ks < 4; ks++) {     // four k16 steps per 64-chunk
            const int k8 = ks * 8;
            uint32_t a[4][4];
#pragma unroll
            for (int mt = 0; mt < 4; mt++) {
                int r = wm + mt * 16 + lr;
                a[mt][0] = Ast[r*WPD + k8 + lc];
                a[mt][1] = Ast[(r+8)*WPD + k8 + lc];
                a[mt][2] = Ast[r*WPD + k8 + lc + 4];
                a[mt][3] = Ast[(r+8)*WPD + k8 + lc + 4];
            }
#pragma unroll
            for (int nt = 0; nt < 4; nt++) {
                int n = wn + nt * 8 + lr;
                uint32_t b0 = Bst[n*WPD + k8 + lc];
                uint32_t b1 = Bst[n*WPD + k8 + lc + 4];
#pragma unroll
                for (int mt = 0; mt < 4; mt++)
                    mma_fp16(acc[mt][nt][0], acc[mt][nt][1],
                             acc[mt][nt][2], acc[mt][nt][3],
                             a[mt][0], a[mt][1], a[mt][2], a[mt][3], b0, b1);
            }
        }
    }

    // Epilogue: z<2 -> packed fp16 [bh][s][dk/2]; z==2 -> fp16x2 transposed.
    uint32_t* opk = (z == 0) ? qf : kf;
#pragma unroll
    for (int mt = 0; mt < 4; mt++) {
#pragma unroll
        for (int nt = 0; nt < 4; nt++) {
            int col = col0 + wn + nt * 8 + 2 * lc;
            float2 bb = *(const float2*)(bias + col);
            int head = col >> 6;
            int dk   = col & 63;
#pragma unroll
            for (int h = 0; h < 2; h++) {
                int row = row0 + wm + mt * 16 + lr + h * 8;
                int bi  = row >> 11;
                int si  = row & (SLEN - 1);
                float vx = acc[mt][nt][2*h + 0] + bb.x;
                float vy = acc[mt][nt][2*h + 1] + bb.y;
                if (z == 2) {
                    float px = __shfl_xor_sync(0xffffffffu, vx, 4);
                    float py = __shfl_xor_sync(0xffffffffu, vy, 4);
                    if (!(lane & 4)) {
                        size_t base = ((size_t)(bi * HNUM + head) * DKQ + dk) * (SLEN/2);
                        vt2[base + (si >> 1)]            = pack_h2(vx, px);
                        vt2[base + (SLEN/2) + (si >> 1)] = pack_h2(vy, py);
                    }
                } else {
                    if (z == 0) { vx *= 0.125f; vy *= 0.125f; }
                    size_t wi = ((size_t)(bi * HNUM + head) * SLEN + si) * 32 + (dk >> 1);
                    opk[wi] = pack_h2(vx, vy);
                }
            }
        }
    }
}

// ---------------- cp.async flash attention: fp16 QK, P in registers (R14/R15) ----------------
// Smem word offsets: Qf 0 | stage s: Kf 2304+4608s, Vt +2304. Total 11520 words.
__global__ __launch_bounds__(128) void attn_mma_kernel(
    const uint32_t* __restrict__ Qf_g, const uint32_t* __restrict__ Kf_g,
    const uint32_t* __restrict__ Vt_g,  float* __restrict__ out)
{
    extern __shared__ uint32_t sm[];
    uint32_t* Qf = sm;
    const uint32_t sm_u = smem_u32(sm);

    const int tid  = threadIdx.x;
    const int w    = tid >> 5;
    const int lane = tid & 31;
    const int lr   = lane >> 2;
    const int lc   = lane & 3;
    const int bh   = blockIdx.x;
    const int qt   = (gridDim.y - 1) - blockIdx.y;

    const uint32_t* Qf_src = Qf_g + ((size_t)bh * SLEN + (size_t)qt * 64) * 32;

    auto issue_kv = [&](int kt, int s) {
        const uint32_t* Kf_s = Kf_g + ((size_t)bh * SLEN + (size_t)kt * 64) * 32;
        const uint32_t* Vt_s = Vt_g + (size_t)bh * DKQ * (SLEN/2) + (size_t)kt * 32;
        const uint32_t kb = sm_u + (uint32_t)(2304 + s*4608) * 4;
#pragma unroll
        for (int it = 0; it < 4; it++) {
            int f = tid + it * 128;          // 0..511 : 64 rows x 8 cp16
            int r = f >> 3;
            int o = (f & 7) * 16;
            uint32_t d = (uint32_t)(r * (WPD*4)) + o;
            cp16(kb + d,            (const char*)(Kf_s + (size_t)r * 32) + o);
            cp16(kb + 2304*4 + d,   (const char*)(Vt_s + (size_t)r * (SLEN/2)) + o);
        }
    };

#pragma unroll
    for (int it = 0; it < 4; it++) {
        int f = tid + it * 128;
        int r = f >> 3;
        int o = (f & 7) * 16;
        uint32_t d = (uint32_t)(r * (WPD*4)) + o;
        cp16(sm_u + d, (const char*)(Qf_src + (size_t)r * 32) + o);
    }
    issue_kv(0, 0);
    CP_COMMIT();

    float accO[8][4];
#pragma unroll
    for (int nf = 0; nf < 8; nf++)
#pragma unroll
        for (int i = 0; i < 4; i++) accO[nf][i] = 0.f;
    float mrow[2] = { -1e30f, -1e30f };
    float lrow[2] = { 0.f, 0.f };

    uint32_t qf_r[4][4];               // Q fragments, kt-invariant
    uint32_t pw[2][8];                 // packed P words = PV A-fragments

    const int qrow0 = qt*64 + w*16 + lr;
    const int qbw   = (w*16 + lr) * WPD;

    for (int kt = 0; kt <= qt; kt++) {
        const int s = kt & 1;
        __syncthreads();                     // stage-s^1 readers (kt-1) done
        if (kt < qt) { issue_kv(kt + 1, s ^ 1); CP_COMMIT(); CP_WAIT1(); }
        else         { CP_WAIT0(); }
        __syncthreads();                     // stage s (and Q at kt=0) visible

        if (kt == 0) {
#pragma unroll
            for (int ks = 0; ks < 4; ks++) {
                const int k8 = ks * 8;
                qf_r[ks][0] = Qf[qbw + k8 + lc];
                qf_r[ks][1] = Qf[qbw + 8*WPD + k8 + lc];
                qf_r[ks][2] = Qf[qbw + k8 + lc + 4];
                qf_r[ks][3] = Qf[qbw + 8*WPD + k8 + lc + 4];
            }
        }

        const uint32_t* Kfs = sm + 2304 + s*4608;
        const uint32_t* Vts = Kfs + 2304;

        // ---- scores: fp16 QK^T ----
        float accS[8][4];
#pragma unroll
        for (int nf = 0; nf < 8; nf++)
#pragma unroll
            for (int i = 0; i < 4; i++) accS[nf][i] = 0.f;

#pragma unroll
        for (int ks = 0; ks < 4; ks++) {
            const int k8 = ks * 8;
#pragma unroll
            for (int nf = 0; nf < 8; nf++) {
                int nb = (nf*8 + lr) * WPD + k8 + lc;
                uint32_t b0 = Kfs[nb], b1 = Kfs[nb + 4];
                mma_fp16(accS[nf][0], accS[nf][1], accS[nf][2], accS[nf][3],
                         qf_r[ks][0], qf_r[ks][1], qf_r[ks][2], qf_r[ks][3], b0, b1);
            }
        }

        if (kt == qt) {
#pragma unroll
            for (int nf = 0; nf < 8; nf++) {
                int gc = kt*64 + nf*8 + 2*lc;
                if (gc     > qrow0)     accS[nf][0] = -1e30f;
                if (gc + 1 > qrow0)     accS[nf][1] = -1e30f;
                if (gc     > qrow0 + 8) accS[nf][2] = -1e30f;
                if (gc + 1 > qrow0 + 8) accS[nf][3] = -1e30f;
            }
        }

        // ---- online softmax; P kept in registers ----
#pragma unroll
        for (int h = 0; h < 2; h++) {
            const int i0 = 2*h, i1 = 2*h + 1;
            float rmax = accS[0][i0];
#pragma unroll
            for (int nf = 0; nf < 8; nf++) {
                rmax = fmaxf(rmax, accS[nf][i0]);
                rmax = fmaxf(rmax, accS[nf][i1]);
            }
            rmax = fmaxf(rmax, __shfl_xor_sync(0xffffffffu, rmax, 1));
            rmax = fmaxf(rmax, __shfl_xor_sync(0xffffffffu, rmax, 2));
            float mn   = fmaxf(mrow[h], rmax);
            float corr = __expf(mrow[h] - mn);
            mrow[h] = mn;
            float rsum = 0.f;
#pragma unroll
            for (int nf = 0; nf < 8; nf++) {
                float e0 = __expf(accS[nf][i0] - mn);
                float e1 = __expf(accS[nf][i1] - mn);
                __half2 hp = __floats2half2_rn(e0, e1);
                pw[h][nf] = *(uint32_t*)&hp;
                rsum += __low2float(hp) + __high2float(hp);
                accO[nf][i0] *= corr;
                accO[nf][i1] *= corr;
            }
            rsum += __shfl_xor_sync(0xffffffffu, rsum, 1);
            rsum += __shfl_xor_sync(0xffffffffu, rsum, 2);
            lrow[h] = lrow[h] * corr + rsum;
        }

        // ---- accO += P @ V (fp16); A-fragments ARE the pw registers ----
#pragma unroll
        for (int ks = 0; ks < 4; ks++) {
            const int k8 = ks * 8;
            uint32_t a0 = pw[0][2*ks];
            uint32_t a1 = pw[1][2*ks];
            uint32_t a2 = pw[0][2*ks + 1];
            uint32_t a3 = pw[1][2*ks + 1];
#pragma unroll
            for (int nf = 0; nf < 8; nf++) {
                int nb = (nf*8 + lr) * WPD + k8 + lc;
                uint32_t b0 = Vts[nb], b1 = Vts[nb + 4];
                mma_fp16(accO[nf][0], accO[nf][1], accO[nf][2], accO[nf][3],
                         a0, a1, a2, a3, b0, b1);
            }
        }
    }

    // ---- epilogue: out[B,S,D] ----
    const int b = bh >> 4, h = bh & 15;
    const float inv0 = 1.f / lrow[0];
    const float inv1 = 1.f / lrow[1];
    const int s0 = qt*64 + w*16 + lr;
    const int s1 = s0 + 8;
#pragma unroll
    for (int nf = 0; nf < 8; nf++) {
        int col = h*DKQ + nf*8 + 2*lc;
        float2 v0 = { accO[nf][0] * inv0, accO[nf][1] * inv0 };
        float2 v1 = { accO[nf][2] * inv1, accO[nf][3] * inv1 };
        *(float2*)(out + ((size_t)b * SLEN + s0) * DDIM + col) = v0;
        *(float2*)(out + ((size_t)b * SLEN + s1) * DDIM + col) = v1;
    }
}

extern "C" void kernel_launch(void* const* d_in, const int* in_sizes, int n_in,
                              void* d_out, int out_size) {
    const float* q  = (const float*)d_in[0];
    const float* k  = (const float*)d_in[1];
    const float* v  = (const float*)d_in[2];
    const float* Wq = (const float*)d_in[3];
    const float* bq = (const float*)d_in[4];
    const float* Wk = (const float*)d_in[5];
    const float* bk = (const float*)d_in[6];
    const float* Wv = (const float*)d_in[7];
    const float* bv = (const float*)d_in[8];
    float* out = (float*)d_out;

    uint32_t *gwt16, *gaf16, *gqf, *gkf, *gvt;
    cudaGetSymbolAddress((void**)&gwt16, g_wt16);
    cudaGetSymbolAddress((void**)&gaf16, g_af16);
    cudaGetSymbolAddress((void**)&gqf,   g_qf16);
    cudaGetSymbolAddress((void**)&gkf,   g_kf16);
    cudaGetSymbolAddress((void**)&gvt,   g_vt2);

    // Fused weight transpose + fp16 pack, one launch for all 3 weights.
    dim3 tgrid(DDIM/32, DDIM/32, 3), tblk(32, 8);
    transpose_pack_kernel<<<tgrid, tblk>>>(
        Wq, Wk, Wv,
        gwt16 + 0*DDIM*DDIM/2, gwt16 + 1*DDIM*DDIM/2, gwt16 + 2*DDIM*DDIM/2);

    // Inputs -> packed fp16, single launch.
    const size_t NA = (size_t)BNUM*SLEN*DDIM;
    const int na4 = (int)(NA/4);
    cvt_f16_kernel<<<dim3((na4+255)/256, 3), 256>>>(
        (const float4*)q, (const float4*)k, (const float4*)v,
        (uint2*)(gaf16 + 0*NA/2), (uint2*)(gaf16 + 1*NA/2), (uint2*)(gaf16 + 2*NA/2), na4);

    // Projections (K-chunk 64, 2-stage); epilogue emits attn-ready formats.
    const int proj_smem = 2 * 2 * 128 * WPD * 4;  // 73728
    cudaFuncSetAttribute(proj_mma_kernel,
        cudaFuncAttributeMaxDynamicSharedMemorySize, proj_smem);
    dim3 pgrid(DDIM/128, (BNUM*SLEN)/128, 3);
    proj_mma_kernel<<<pgrid, 256, proj_smem>>>(
        gaf16 + 0*NA/2, gaf16 + 1*NA/2, gaf16 + 2*NA/2,
        gwt16 + 0*DDIM*DDIM/2, gwt16 + 1*DDIM*DDIM/2, gwt16 + 2*DDIM*DDIM/2,
        bq, bk, bv,
        gqf, gkf, gvt);

    // Attention (fp16 QK, smem 46080 B — unchanged R15).
    const int attn_smem = 11520 * 4;              // 46080
    cudaFuncSetAttribute(attn_mma_kernel,
        cudaFuncAttributeMaxDynamicSharedMemorySize, attn_smem);
    attn_mma_kernel<<<dim3(BNUM*HNUM, SLEN/64), 128, attn_smem>>>(
        gqf, gkf, gvt, out);
}